// round 1
// baseline (speedup 1.0000x reference)
#include <cuda_runtime.h>
#include <math.h>

#define D_MODEL   2048
#define D_INNER   4096
#define NHEADS    64
#define HEAD_DIM  64
#define D_STATE   128
#define CHUNK     256
#define CONV_DIM  4352            // D_INNER + 2*D_STATE
#define D_IN_PROJ 8512            // 2*D_INNER + 2*D_STATE + NHEADS
#define BATCH     2
#define SEQ       2048
#define NTOK      (BATCH*SEQ)     // 4096
#define NCHUNK    (SEQ/CHUNK)     // 8

// ---------------- scratch (device globals: no allocation allowed) ----------------
__device__ float g_zxbcdt[NTOK * D_IN_PROJ];                       // 139 MB
__device__ float g_xbc[NTOK * CONV_DIM];                           // 71 MB
__device__ float g_dt [BATCH*NHEADS*NCHUNK*CHUNK];                 // dt softplus, [b][h][c][t]
__device__ float g_acs[BATCH*NHEADS*NCHUNK*CHUNK];                 // cumsum(dA), [b][h][c][t]
__device__ float g_ctot[BATCH*NHEADS*NCHUNK];                      // chunk totals
__device__ float g_GT[BATCH*NCHUNK*CHUNK*CHUNK];                   // G^T: [bc][s][t]
__device__ float g_S [BATCH*NCHUNK*NHEADS*HEAD_DIM*D_STATE];       // chunk states
__device__ float g_P [BATCH*NCHUNK*NHEADS*HEAD_DIM*D_STATE];       // entering states
__device__ float g_y [NTOK*D_INNER];                               // SSD output
__device__ float g_xn[NTOK*D_INNER];                               // normed

// ---------------- classic fp32 SGEMM: C[M,N] = A[M,K] @ B[K,N] ----------------
// 128x128 tile, BK=8, 256 threads, 8x8 per-thread microtile. M%128==0, K%8==0 assumed.
__global__ __launch_bounds__(256) void sgemm128(const float* __restrict__ A,
                                                const float* __restrict__ B,
                                                float* __restrict__ C,
                                                int M, int N, int K) {
    __shared__ __align__(16) float As[8][128];
    __shared__ __align__(16) float Bs[8][128];
    int bx = blockIdx.x, by = blockIdx.y;
    int tid = threadIdx.x;

    int arow = tid >> 1;            // 0..127
    int acol = (tid & 1) * 4;       // 0 or 4
    int brow = tid >> 5;            // 0..7
    int bcol = (tid & 31) * 4;      // 0..124

    int r0 = (tid >> 4) * 8;        // row block within tile
    int c0 = (tid & 15) * 8;        // col block within tile

    const float* Ab = A + (size_t)(by * 128) * K;
    float acc[8][8];
#pragma unroll
    for (int i = 0; i < 8; i++)
#pragma unroll
        for (int j = 0; j < 8; j++) acc[i][j] = 0.f;

    for (int k0 = 0; k0 < K; k0 += 8) {
        float4 av = *(const float4*)(Ab + (size_t)arow * K + k0 + acol);
        As[acol + 0][arow] = av.x;
        As[acol + 1][arow] = av.y;
        As[acol + 2][arow] = av.z;
        As[acol + 3][arow] = av.w;

        int gc = bx * 128 + bcol;
        float4 bv = make_float4(0.f, 0.f, 0.f, 0.f);
        if (gc < N) bv = *(const float4*)(B + (size_t)(k0 + brow) * N + gc);
        *(float4*)&Bs[brow][bcol] = bv;
        __syncthreads();

#pragma unroll
        for (int k = 0; k < 8; k++) {
            float4 a0 = *(const float4*)&As[k][r0];
            float4 a1 = *(const float4*)&As[k][r0 + 4];
            float4 b0 = *(const float4*)&Bs[k][c0];
            float4 b1 = *(const float4*)&Bs[k][c0 + 4];
            float a[8] = {a0.x, a0.y, a0.z, a0.w, a1.x, a1.y, a1.z, a1.w};
            float b[8] = {b0.x, b0.y, b0.z, b0.w, b1.x, b1.y, b1.z, b1.w};
#pragma unroll
            for (int i = 0; i < 8; i++)
#pragma unroll
                for (int j = 0; j < 8; j++) acc[i][j] += a[i] * b[j];
        }
        __syncthreads();
    }

#pragma unroll
    for (int i = 0; i < 8; i++) {
        int crow = by * 128 + r0 + i;
        int cc = bx * 128 + c0;
        if (cc < N)
            *(float4*)(C + (size_t)crow * N + cc) =
                make_float4(acc[i][0], acc[i][1], acc[i][2], acc[i][3]);
        if (cc + 4 < N)
            *(float4*)(C + (size_t)crow * N + cc + 4) =
                make_float4(acc[i][4], acc[i][5], acc[i][6], acc[i][7]);
    }
}

// ---------------- causal conv1d (K=4) + SiLU over xbc channels ----------------
__global__ void conv_kernel(const float* __restrict__ w, const float* __restrict__ bias) {
    int idx = blockIdx.x * blockDim.x + threadIdx.x;
    if (idx >= NTOK * CONV_DIM) return;
    int c = idx % CONV_DIM;
    int tok = idx / CONV_DIM;
    int b = tok / SEQ, t = tok % SEQ;
    float acc = bias[c];
#pragma unroll
    for (int k = 0; k < 4; k++) {
        int tp = t - 3 + k;
        if (tp >= 0)
            acc += g_zxbcdt[(size_t)(b * SEQ + tp) * D_IN_PROJ + D_INNER + c] * w[c * 4 + k];
    }
    g_xbc[idx] = acc / (1.f + expf(-acc));   // silu
}

// ---------------- dt = softplus(raw + bias); dA = dt*A; per-chunk inclusive cumsum ----------------
__global__ void dt_scan_kernel(const float* __restrict__ dt_bias, const float* __restrict__ A) {
    int c = blockIdx.x, h = blockIdx.y, b = blockIdx.z;
    int t = threadIdx.x;  // 0..255
    int l = c * CHUNK + t;
    float raw = g_zxbcdt[(size_t)(b * SEQ + l) * D_IN_PROJ + (D_INNER + CONV_DIM) + h] + dt_bias[h];
    float dtv = (raw > 20.f) ? raw : log1pf(expf(raw));
    int base = ((b * NHEADS + h) * NCHUNK + c) * CHUNK;
    g_dt[base + t] = dtv;
    __shared__ float sb[CHUNK];
    sb[t] = dtv * A[h];
    __syncthreads();
    for (int off = 1; off < CHUNK; off <<= 1) {
        float v = (t >= off) ? sb[t - off] : 0.f;
        __syncthreads();
        sb[t] += v;
        __syncthreads();
    }
    g_acs[base + t] = sb[t];
    if (t == CHUNK - 1) g_ctot[(b * NHEADS + h) * NCHUNK + c] = sb[t];
}

// ---------------- G^T[bc][s][t] = sum_n C[t,n]*B[s,n]  (head-independent, NGROUPS=1) ----------------
__global__ __launch_bounds__(256) void gmat_kernel() {
    int bc = blockIdx.z;            // 0..15
    int b = bc >> 3, c = bc & 7;
    int s0 = blockIdx.x * 64, t0 = blockIdx.y * 64;
    __shared__ __align__(16) float Ct[64][65];
    __shared__ __align__(16) float Bt[64][65];
    int tid = threadIdx.x;
    int ti = (tid / 16) * 4, sj = (tid % 16) * 4;
    float acc[4][4];
#pragma unroll
    for (int i = 0; i < 4; i++)
#pragma unroll
        for (int j = 0; j < 4; j++) acc[i][j] = 0.f;

    for (int k0 = 0; k0 < D_STATE; k0 += 64) {
        for (int idx = tid; idx < 64 * 64; idx += 256) {
            int r = idx >> 6, kk = idx & 63;
            Ct[r][kk] = g_xbc[(size_t)(b * SEQ + c * CHUNK + t0 + r) * CONV_DIM + 4224 + k0 + kk];
            Bt[r][kk] = g_xbc[(size_t)(b * SEQ + c * CHUNK + s0 + r) * CONV_DIM + 4096 + k0 + kk];
        }
        __syncthreads();
        for (int k = 0; k < 64; k++) {
            float a[4], bb[4];
#pragma unroll
            for (int i = 0; i < 4; i++) { a[i] = Ct[ti + i][k]; bb[i] = Bt[sj + i][k]; }
#pragma unroll
            for (int i = 0; i < 4; i++)
#pragma unroll
                for (int j = 0; j < 4; j++) acc[i][j] += a[i] * bb[j];
        }
        __syncthreads();
    }
#pragma unroll
    for (int j = 0; j < 4; j++)
#pragma unroll
        for (int i = 0; i < 4; i++)
            g_GT[(size_t)(bc * CHUNK + s0 + sj + j) * CHUNK + t0 + ti + i] = acc[i][j];
}

// ---------------- Y_diag[t,p] = sum_s G[t,s]*exp(acs[t]-acs[s])*dt[s]*x[s,p] ----------------
__global__ __launch_bounds__(256) void ydiag_kernel() {
    int c = blockIdx.x, h = blockIdx.y, b = blockIdx.z;
    int tid = threadIdx.x;
    __shared__ float acs[CHUNK];
    __shared__ float dts[CHUNK];
    __shared__ __align__(16) float Ms[32][260];   // M^T: [s][t]
    __shared__ __align__(16) float Xs[32][68];    // dt-weighted x: [s][p]
    int base = ((b * NHEADS + h) * NCHUNK + c) * CHUNK;
    acs[tid] = g_acs[base + tid];
    dts[tid] = g_dt[base + tid];
    __syncthreads();

    float a_t = acs[tid];
    int bcq = b * NCHUNK + c;
    int i0 = (tid / 8) * 8;   // t-rows
    int j0 = (tid % 8) * 8;   // p-cols
    float acc[8][8];
#pragma unroll
    for (int i = 0; i < 8; i++)
#pragma unroll
        for (int j = 0; j < 8; j++) acc[i][j] = 0.f;

    for (int s0 = 0; s0 < CHUNK; s0 += 32) {
        // fill M^T column (thread owns t = tid)
        for (int s = 0; s < 32; s++) {
            int sg = s0 + s;
            float m = 0.f;
            if (sg <= tid)
                m = g_GT[(size_t)(bcq * CHUNK + sg) * CHUNK + tid] * expf(a_t - acs[sg]);
            Ms[s][tid] = m;
        }
        // fill dt-weighted x tile
        for (int idx = tid; idx < 32 * 64; idx += 256) {
            int s = idx >> 6, p = idx & 63;
            int sg = s0 + s;
            Xs[s][p] = dts[sg] *
                g_xbc[(size_t)(b * SEQ + c * CHUNK + sg) * CONV_DIM + h * HEAD_DIM + p];
        }
        __syncthreads();
        for (int s = 0; s < 32; s++) {
            float4 a0 = *(const float4*)&Ms[s][i0];
            float4 a1 = *(const float4*)&Ms[s][i0 + 4];
            float4 b0 = *(const float4*)&Xs[s][j0];
            float4 b1 = *(const float4*)&Xs[s][j0 + 4];
            float a[8] = {a0.x, a0.y, a0.z, a0.w, a1.x, a1.y, a1.z, a1.w};
            float bb[8] = {b0.x, b0.y, b0.z, b0.w, b1.x, b1.y, b1.z, b1.w};
#pragma unroll
            for (int i = 0; i < 8; i++)
#pragma unroll
                for (int j = 0; j < 8; j++) acc[i][j] += a[i] * bb[j];
        }
        __syncthreads();
    }
#pragma unroll
    for (int i = 0; i < 8; i++) {
        int t = i0 + i;
        float* yp = &g_y[(size_t)(b * SEQ + c * CHUNK + t) * D_INNER + h * HEAD_DIM + j0];
        *(float4*)yp = make_float4(acc[i][0], acc[i][1], acc[i][2], acc[i][3]);
        *(float4*)(yp + 4) = make_float4(acc[i][4], acc[i][5], acc[i][6], acc[i][7]);
    }
}

// ---------------- S[p,n] = sum_t B[t,n]*exp(acs_last - acs[t])*dt[t]*x[t,p] ----------------
__global__ __launch_bounds__(256) void states_kernel() {
    int c = blockIdx.x, h = blockIdx.y, b = blockIdx.z;
    int tid = threadIdx.x;
    __shared__ float acs[CHUNK], dts[CHUNK], wts[CHUNK];
    __shared__ __align__(16) float wxs[32][68];    // [t][p]
    __shared__ __align__(16) float Bsh[32][132];   // [t][n]
    int base = ((b * NHEADS + h) * NCHUNK + c) * CHUNK;
    acs[tid] = g_acs[base + tid];
    dts[tid] = g_dt[base + tid];
    __syncthreads();
    float alast = acs[CHUNK - 1];
    wts[tid] = expf(alast - acs[tid]) * dts[tid];
    __syncthreads();

    int p0 = (tid / 16) * 4, n0 = (tid % 16) * 8;
    float acc[4][8];
#pragma unroll
    for (int i = 0; i < 4; i++)
#pragma unroll
        for (int j = 0; j < 8; j++) acc[i][j] = 0.f;

    for (int t0 = 0; t0 < CHUNK; t0 += 32) {
        for (int idx = tid; idx < 32 * 64; idx += 256) {
            int tt = idx >> 6, p = idx & 63;
            int tg = t0 + tt;
            wxs[tt][p] = wts[tg] *
                g_xbc[(size_t)(b * SEQ + c * CHUNK + tg) * CONV_DIM + h * HEAD_DIM + p];
        }
        for (int idx = tid; idx < 32 * 128; idx += 256) {
            int tt = idx >> 7, n = idx & 127;
            Bsh[tt][n] = g_xbc[(size_t)(b * SEQ + c * CHUNK + t0 + tt) * CONV_DIM + 4096 + n];
        }
        __syncthreads();
        for (int t = 0; t < 32; t++) {
            float4 a = *(const float4*)&wxs[t][p0];
            float4 b0 = *(const float4*)&Bsh[t][n0];
            float4 b1 = *(const float4*)&Bsh[t][n0 + 4];
            float av[4] = {a.x, a.y, a.z, a.w};
            float bv[8] = {b0.x, b0.y, b0.z, b0.w, b1.x, b1.y, b1.z, b1.w};
#pragma unroll
            for (int i = 0; i < 4; i++)
#pragma unroll
                for (int j = 0; j < 8; j++) acc[i][j] += av[i] * bv[j];
        }
        __syncthreads();
    }
    int sbase = ((b * NCHUNK + c) * NHEADS + h) * HEAD_DIM;
#pragma unroll
    for (int i = 0; i < 4; i++) {
        float* sp = &g_S[(size_t)(sbase + p0 + i) * D_STATE + n0];
        *(float4*)sp = make_float4(acc[i][0], acc[i][1], acc[i][2], acc[i][3]);
        *(float4*)(sp + 4) = make_float4(acc[i][4], acc[i][5], acc[i][6], acc[i][7]);
    }
}

// ---------------- inter-chunk recurrence: P[c] = entering state of chunk c ----------------
__global__ void recur_kernel() {
    int idx = blockIdx.x * 256 + threadIdx.x;   // over BATCH*NHEADS*HEAD_DIM*D_STATE
    int n = idx & 127;
    int p = (idx >> 7) & 63;
    int h = (idx >> 13) & 63;
    int b = idx >> 19;
    float acc = 0.f;
#pragma unroll
    for (int c = 0; c < NCHUNK; c++) {
        size_t off = (size_t)(((b * NCHUNK + c) * NHEADS + h) * HEAD_DIM + p) * D_STATE + n;
        g_P[off] = acc;
        acc = acc * expf(g_ctot[(b * NHEADS + h) * NCHUNK + c]) + g_S[off];
    }
}

// ---------------- Y += exp(acs[t]) * (C @ P^T) + x*D  ----------------
__global__ __launch_bounds__(256) void yoff_kernel(const float* __restrict__ Dskip) {
    int c = blockIdx.x, h = blockIdx.y, b = blockIdx.z;
    int tid = threadIdx.x;
    __shared__ float acs[CHUNK];
    __shared__ __align__(16) float Cs[32][260];   // [n][t]
    __shared__ __align__(16) float Ps[32][68];    // [n][p]
    int base = ((b * NHEADS + h) * NCHUNK + c) * CHUNK;
    acs[tid] = g_acs[base + tid];
    __syncthreads();

    int i0 = (tid / 8) * 8;   // t
    int j0 = (tid % 8) * 8;   // p
    int pbase = ((b * NCHUNK + c) * NHEADS + h) * HEAD_DIM;
    float acc[8][8];
#pragma unroll
    for (int i = 0; i < 8; i++)
#pragma unroll
        for (int j = 0; j < 8; j++) acc[i][j] = 0.f;

    for (int n0 = 0; n0 < D_STATE; n0 += 32) {
        for (int idx = tid; idx < 32 * 256; idx += 256) {
            int nt = idx & 31, t = idx >> 5;
            Cs[nt][t] = g_xbc[(size_t)(b * SEQ + c * CHUNK + t) * CONV_DIM + 4224 + n0 + nt];
        }
        for (int idx = tid; idx < 32 * 64; idx += 256) {
            int nt = idx & 31, p = idx >> 5;
            Ps[nt][p] = g_P[(size_t)(pbase + p) * D_STATE + n0 + nt];
        }
        __syncthreads();
        for (int n = 0; n < 32; n++) {
            float4 a0 = *(const float4*)&Cs[n][i0];
            float4 a1 = *(const float4*)&Cs[n][i0 + 4];
            float4 b0 = *(const float4*)&Ps[n][j0];
            float4 b1 = *(const float4*)&Ps[n][j0 + 4];
            float a[8] = {a0.x, a0.y, a0.z, a0.w, a1.x, a1.y, a1.z, a1.w};
            float bb[8] = {b0.x, b0.y, b0.z, b0.w, b1.x, b1.y, b1.z, b1.w};
#pragma unroll
            for (int i = 0; i < 8; i++)
#pragma unroll
                for (int j = 0; j < 8; j++) acc[i][j] += a[i] * bb[j];
        }
        __syncthreads();
    }
    float Dh = Dskip[h];
#pragma unroll
    for (int i = 0; i < 8; i++) {
        int t = i0 + i;
        float e = expf(acs[t]);
        size_t ybase = (size_t)(b * SEQ + c * CHUNK + t) * D_INNER + h * HEAD_DIM + j0;
        size_t xbase = (size_t)(b * SEQ + c * CHUNK + t) * CONV_DIM + h * HEAD_DIM + j0;
        float4 y0 = *(float4*)&g_y[ybase];
        float4 y1 = *(float4*)&g_y[ybase + 4];
        float4 x0 = *(const float4*)&g_xbc[xbase];
        float4 x1 = *(const float4*)&g_xbc[xbase + 4];
        y0.x += acc[i][0] * e + x0.x * Dh;  y0.y += acc[i][1] * e + x0.y * Dh;
        y0.z += acc[i][2] * e + x0.z * Dh;  y0.w += acc[i][3] * e + x0.w * Dh;
        y1.x += acc[i][4] * e + x1.x * Dh;  y1.y += acc[i][5] * e + x1.y * Dh;
        y1.z += acc[i][6] * e + x1.z * Dh;  y1.w += acc[i][7] * e + x1.w * Dh;
        *(float4*)&g_y[ybase] = y0;
        *(float4*)&g_y[ybase + 4] = y1;
    }
}

// ---------------- gated RMSNorm: xn = (y*silu(z)) * rsqrt(mean+eps) * w ----------------
__global__ __launch_bounds__(256) void norm_kernel(const float* __restrict__ nw) {
    int tok = blockIdx.x;
    int tid = threadIdx.x;
    __shared__ float v[D_INNER];
    __shared__ float red[256];
    float s = 0.f;
#pragma unroll
    for (int k = 0; k < 16; k++) {
        int d = tid + k * 256;
        float yv = g_y[(size_t)tok * D_INNER + d];
        float zv = g_zxbcdt[(size_t)tok * D_IN_PROJ + d];
        float x = yv * (zv / (1.f + expf(-zv)));
        v[d] = x;
        s += x * x;
    }
    red[tid] = s;
    __syncthreads();
    for (int off = 128; off > 0; off >>= 1) {
        if (tid < off) red[tid] += red[tid + off];
        __syncthreads();
    }
    float scale = rsqrtf(red[0] / (float)D_INNER + 1e-5f);
#pragma unroll
    for (int k = 0; k < 16; k++) {
        int d = tid + k * 256;
        g_xn[(size_t)tok * D_INNER + d] = v[d] * scale * nw[d];
    }
}

// ---------------- launch ----------------
extern "C" void kernel_launch(void* const* d_in, const int* in_sizes, int n_in,
                              void* d_out, int out_size) {
    const float* hidden  = (const float*)d_in[0];
    const float* W_in    = (const float*)d_in[1];
    const float* conv_w  = (const float*)d_in[2];
    const float* conv_b  = (const float*)d_in[3];
    const float* A       = (const float*)d_in[4];
    const float* Dsk     = (const float*)d_in[5];
    const float* dt_bias = (const float*)d_in[6];
    const float* norm_w  = (const float*)d_in[7];
    const float* W_out   = (const float*)d_in[8];
    float* out = (float*)d_out;

    void* p;
    cudaGetSymbolAddress(&p, g_zxbcdt); float* zx = (float*)p;
    cudaGetSymbolAddress(&p, g_xn);     float* xn = (float*)p;

    // 1. in_proj
    sgemm128<<<dim3((D_IN_PROJ + 127) / 128, NTOK / 128), 256>>>(hidden, W_in, zx,
                                                                 NTOK, D_IN_PROJ, D_MODEL);
    // 2. conv + silu
    conv_kernel<<<(NTOK * CONV_DIM + 255) / 256, 256>>>(conv_w, conv_b);
    // 3. dt softplus + dA cumsum
    dt_scan_kernel<<<dim3(NCHUNK, NHEADS, BATCH), CHUNK>>>(dt_bias, A);
    // 4. G = C B^T (head-independent)
    gmat_kernel<<<dim3(4, 4, BATCH * NCHUNK), 256>>>();
    // 5. Y_diag
    ydiag_kernel<<<dim3(NCHUNK, NHEADS, BATCH), 256>>>();
    // 6. chunk states
    states_kernel<<<dim3(NCHUNK, NHEADS, BATCH), 256>>>();
    // 7. recurrence
    recur_kernel<<<(BATCH * NHEADS * HEAD_DIM * D_STATE) / 256, 256>>>();
    // 8. Y_off + D skip
    yoff_kernel<<<dim3(NCHUNK, NHEADS, BATCH), 256>>>(Dsk);
    // 9. gated rmsnorm
    norm_kernel<<<NTOK, 256>>>(norm_w);
    // 10. out_proj
    sgemm128<<<dim3(D_MODEL / 128, NTOK / 128), 256>>>(xn, W_out, out,
                                                       NTOK, D_MODEL, D_INNER);
}

// round 3
// speedup vs baseline: 2.0175x; 2.0175x over previous
#include <cuda_runtime.h>
#include <cstdint>
#include <math.h>

#define D_MODEL   2048
#define D_INNER   4096
#define NHEADS    64
#define HEAD_DIM  64
#define D_STATE   128
#define CHUNK     256
#define CONV_DIM  4352            // D_INNER + 2*D_STATE
#define D_IN_PROJ 8512            // 2*D_INNER + 2*D_STATE + NHEADS
#define BATCH     2
#define SEQ       2048
#define NTOK      (BATCH*SEQ)     // 4096
#define NCHUNK    (SEQ/CHUNK)     // 8

// ---------------- scratch (device globals: no allocation allowed) ----------------
__device__ float g_zxbcdt[NTOK * D_IN_PROJ];                       // 139 MB
__device__ float g_xbc[NTOK * CONV_DIM];                           // 71 MB
__device__ float g_dt [BATCH*NHEADS*NCHUNK*CHUNK];                 // dt softplus, [b][h][c][t]
__device__ float g_acs[BATCH*NHEADS*NCHUNK*CHUNK];                 // cumsum(dA), [b][h][c][t]
__device__ float g_ctot[BATCH*NHEADS*NCHUNK];                      // chunk totals
__device__ float g_GT[BATCH*NCHUNK*CHUNK*CHUNK];                   // G^T: [bc][s][t]
__device__ float g_S [BATCH*NCHUNK*NHEADS*HEAD_DIM*D_STATE];       // chunk states
__device__ float g_P [BATCH*NCHUNK*NHEADS*HEAD_DIM*D_STATE];       // entering states
__device__ float g_y [NTOK*D_INNER];                               // SSD output
__device__ float g_xn[NTOK*D_INNER];                               // normed

// ---------------- tf32 helpers ----------------
__device__ __forceinline__ uint32_t f2tf32(float x) {
    uint32_t r;
    asm("cvt.rna.tf32.f32 %0, %1;" : "=r"(r) : "f"(x));
    return r;
}

__device__ __forceinline__ void mma_tf32(float c[4],
                                         uint32_t a0, uint32_t a1, uint32_t a2, uint32_t a3,
                                         uint32_t b0, uint32_t b1) {
    asm volatile(
        "mma.sync.aligned.m16n8k8.row.col.f32.tf32.tf32.f32 "
        "{%0,%1,%2,%3},{%4,%5,%6,%7},{%8,%9},{%0,%1,%2,%3};"
        : "+f"(c[0]), "+f"(c[1]), "+f"(c[2]), "+f"(c[3])
        : "r"(a0), "r"(a1), "r"(a2), "r"(a3), "r"(b0), "r"(b1));
}

// ---------------- tf32 tensor-core GEMM: C[M,N] = A[M,K] @ B[K,N] ----------------
// 128x128 tile, BK=16, 256 threads (8 warps, 2x4), warp tile 64x32 (m16n8k8).
// Requires: M%128==0, K%16==0, N%4==0. N is bounds-checked.
__global__ __launch_bounds__(256, 2) void tf32gemm(const float* __restrict__ A,
                                                   const float* __restrict__ B,
                                                   float* __restrict__ C,
                                                   int M, int N, int K) {
    __shared__ uint32_t As[16][132];   // [k][m], padded
    __shared__ uint32_t Bs[16][132];   // [k][n], padded

    int tid = threadIdx.x;
    int lane = tid & 31, wid = tid >> 5;
    int wm = wid & 1, wn = wid >> 1;         // warp grid 2(m) x 4(n)
    int gID = lane >> 2, tig = lane & 3;
    int bx = blockIdx.x, by = blockIdx.y;

    // A loader mapping: 128 rows x 16 k; thread -> (row, kgroup of 8)
    int arow = tid >> 1, ak = (tid & 1) * 8;
    const float* Ap = A + (size_t)(by * 128 + arow) * K + ak;

    // B loader mapping: 16 rows x 128 n; thread -> (k in 0..7, n*4); handles k and k+8
    int bn = (tid & 31) * 4, bk = tid >> 5;
    int gbn = bx * 128 + bn;
    bool bok = gbn < N;
    const float* Bp = B + (size_t)bk * N + gbn;

    float4 pa0, pa1, pb0, pb1;

    float acc[4][4][4];
#pragma unroll
    for (int i = 0; i < 4; i++)
#pragma unroll
        for (int j = 0; j < 4; j++)
#pragma unroll
            for (int q = 0; q < 4; q++) acc[i][j][q] = 0.f;

    // initial load
    pa0 = *(const float4*)(Ap + 0);
    pa1 = *(const float4*)(Ap + 4);
    if (bok) {
        pb0 = *(const float4*)(Bp);
        pb1 = *(const float4*)(Bp + (size_t)8 * N);
    } else {
        pb0 = pb1 = make_float4(0.f, 0.f, 0.f, 0.f);
    }
    // store to smem (with tf32 rounding)
    As[ak + 0][arow] = f2tf32(pa0.x); As[ak + 1][arow] = f2tf32(pa0.y);
    As[ak + 2][arow] = f2tf32(pa0.z); As[ak + 3][arow] = f2tf32(pa0.w);
    As[ak + 4][arow] = f2tf32(pa1.x); As[ak + 5][arow] = f2tf32(pa1.y);
    As[ak + 6][arow] = f2tf32(pa1.z); As[ak + 7][arow] = f2tf32(pa1.w);
    Bs[bk][bn + 0] = f2tf32(pb0.x); Bs[bk][bn + 1] = f2tf32(pb0.y);
    Bs[bk][bn + 2] = f2tf32(pb0.z); Bs[bk][bn + 3] = f2tf32(pb0.w);
    Bs[bk + 8][bn + 0] = f2tf32(pb1.x); Bs[bk + 8][bn + 1] = f2tf32(pb1.y);
    Bs[bk + 8][bn + 2] = f2tf32(pb1.z); Bs[bk + 8][bn + 3] = f2tf32(pb1.w);
    __syncthreads();

    for (int k0 = 16;; k0 += 16) {
        bool more = (k0 < K);
        if (more) {
            pa0 = *(const float4*)(Ap + k0);
            pa1 = *(const float4*)(Ap + k0 + 4);
            if (bok) {
                pb0 = *(const float4*)(Bp + (size_t)k0 * N);
                pb1 = *(const float4*)(Bp + (size_t)(k0 + 8) * N);
            }
        }

#pragma unroll
        for (int kk = 0; kk < 16; kk += 8) {
            uint32_t af[4][4], bf[4][2];
#pragma unroll
            for (int im = 0; im < 4; im++) {
                int row = wm * 64 + im * 16 + gID;
                af[im][0] = As[kk + tig][row];
                af[im][1] = As[kk + tig][row + 8];
                af[im][2] = As[kk + 4 + tig][row];
                af[im][3] = As[kk + 4 + tig][row + 8];
            }
#pragma unroll
            for (int in_ = 0; in_ < 4; in_++) {
                int col = wn * 32 + in_ * 8 + gID;
                bf[in_][0] = Bs[kk + tig][col];
                bf[in_][1] = Bs[kk + 4 + tig][col];
            }
#pragma unroll
            for (int im = 0; im < 4; im++)
#pragma unroll
                for (int in_ = 0; in_ < 4; in_++)
                    mma_tf32(acc[im][in_], af[im][0], af[im][1], af[im][2], af[im][3],
                             bf[in_][0], bf[in_][1]);
        }

        if (!more) break;
        __syncthreads();
        As[ak + 0][arow] = f2tf32(pa0.x); As[ak + 1][arow] = f2tf32(pa0.y);
        As[ak + 2][arow] = f2tf32(pa0.z); As[ak + 3][arow] = f2tf32(pa0.w);
        As[ak + 4][arow] = f2tf32(pa1.x); As[ak + 5][arow] = f2tf32(pa1.y);
        As[ak + 6][arow] = f2tf32(pa1.z); As[ak + 7][arow] = f2tf32(pa1.w);
        Bs[bk][bn + 0] = f2tf32(pb0.x); Bs[bk][bn + 1] = f2tf32(pb0.y);
        Bs[bk][bn + 2] = f2tf32(pb0.z); Bs[bk][bn + 3] = f2tf32(pb0.w);
        Bs[bk + 8][bn + 0] = f2tf32(pb1.x); Bs[bk + 8][bn + 1] = f2tf32(pb1.y);
        Bs[bk + 8][bn + 2] = f2tf32(pb1.z); Bs[bk + 8][bn + 3] = f2tf32(pb1.w);
        __syncthreads();
    }

    // epilogue
#pragma unroll
    for (int im = 0; im < 4; im++) {
#pragma unroll
        for (int in_ = 0; in_ < 4; in_++) {
            int r = by * 128 + wm * 64 + im * 16 + gID;
            int cc = bx * 128 + wn * 32 + in_ * 8 + 2 * tig;
            if (cc < N) {
                float2 v0 = make_float2(acc[im][in_][0], acc[im][in_][1]);
                float2 v1 = make_float2(acc[im][in_][2], acc[im][in_][3]);
                *(float2*)&C[(size_t)r * N + cc] = v0;
                *(float2*)&C[(size_t)(r + 8) * N + cc] = v1;
            }
        }
    }
}

// ---------------- causal conv1d (K=4) + SiLU over xbc channels ----------------
__global__ void conv_kernel(const float* __restrict__ w, const float* __restrict__ bias) {
    int idx = blockIdx.x * blockDim.x + threadIdx.x;
    if (idx >= NTOK * CONV_DIM) return;
    int c = idx % CONV_DIM;
    int tok = idx / CONV_DIM;
    int b = tok / SEQ, t = tok % SEQ;
    float acc = bias[c];
#pragma unroll
    for (int k = 0; k < 4; k++) {
        int tp = t - 3 + k;
        if (tp >= 0)
            acc += g_zxbcdt[(size_t)(b * SEQ + tp) * D_IN_PROJ + D_INNER + c] * w[c * 4 + k];
    }
    g_xbc[idx] = acc / (1.f + expf(-acc));   // silu
}

// ---------------- dt = softplus(raw + bias); dA = dt*A; per-chunk inclusive cumsum ----------------
__global__ void dt_scan_kernel(const float* __restrict__ dt_bias, const float* __restrict__ A) {
    int c = blockIdx.x, h = blockIdx.y, b = blockIdx.z;
    int t = threadIdx.x;  // 0..255
    int l = c * CHUNK + t;
    float raw = g_zxbcdt[(size_t)(b * SEQ + l) * D_IN_PROJ + (D_INNER + CONV_DIM) + h] + dt_bias[h];
    float dtv = (raw > 20.f) ? raw : log1pf(expf(raw));
    int base = ((b * NHEADS + h) * NCHUNK + c) * CHUNK;
    g_dt[base + t] = dtv;
    __shared__ float sb[CHUNK];
    sb[t] = dtv * A[h];
    __syncthreads();
    for (int off = 1; off < CHUNK; off <<= 1) {
        float v = (t >= off) ? sb[t - off] : 0.f;
        __syncthreads();
        sb[t] += v;
        __syncthreads();
    }
    g_acs[base + t] = sb[t];
    if (t == CHUNK - 1) g_ctot[(b * NHEADS + h) * NCHUNK + c] = sb[t];
}

// ---------------- G^T[bc][s][t] = sum_n C[t,n]*B[s,n]  (head-independent, NGROUPS=1) ----------------
__global__ __launch_bounds__(256) void gmat_kernel() {
    int bc = blockIdx.z;            // 0..15
    int b = bc >> 3, c = bc & 7;
    int s0 = blockIdx.x * 64, t0 = blockIdx.y * 64;
    __shared__ __align__(16) float Ct[64][65];
    __shared__ __align__(16) float Bt[64][65];
    int tid = threadIdx.x;
    int ti = (tid / 16) * 4, sj = (tid % 16) * 4;
    float acc[4][4];
#pragma unroll
    for (int i = 0; i < 4; i++)
#pragma unroll
        for (int j = 0; j < 4; j++) acc[i][j] = 0.f;

    for (int k0 = 0; k0 < D_STATE; k0 += 64) {
        for (int idx = tid; idx < 64 * 64; idx += 256) {
            int r = idx >> 6, kk = idx & 63;
            Ct[r][kk] = g_xbc[(size_t)(b * SEQ + c * CHUNK + t0 + r) * CONV_DIM + 4224 + k0 + kk];
            Bt[r][kk] = g_xbc[(size_t)(b * SEQ + c * CHUNK + s0 + r) * CONV_DIM + 4096 + k0 + kk];
        }
        __syncthreads();
        for (int k = 0; k < 64; k++) {
            float a[4], bb[4];
#pragma unroll
            for (int i = 0; i < 4; i++) { a[i] = Ct[ti + i][k]; bb[i] = Bt[sj + i][k]; }
#pragma unroll
            for (int i = 0; i < 4; i++)
#pragma unroll
                for (int j = 0; j < 4; j++) acc[i][j] += a[i] * bb[j];
        }
        __syncthreads();
    }
#pragma unroll
    for (int j = 0; j < 4; j++)
#pragma unroll
        for (int i = 0; i < 4; i++)
            g_GT[(size_t)(bc * CHUNK + s0 + sj + j) * CHUNK + t0 + ti + i] = acc[i][j];
}

// ---------------- Y_diag[t,p] = sum_s G[t,s]*exp(acs[t]-acs[s])*dt[s]*x[s,p] ----------------
__global__ __launch_bounds__(256) void ydiag_kernel() {
    int c = blockIdx.x, h = blockIdx.y, b = blockIdx.z;
    int tid = threadIdx.x;
    __shared__ float acs[CHUNK];
    __shared__ float dts[CHUNK];
    __shared__ __align__(16) float Ms[32][260];   // M^T: [s][t]
    __shared__ __align__(16) float Xs[32][68];    // dt-weighted x: [s][p]
    int base = ((b * NHEADS + h) * NCHUNK + c) * CHUNK;
    acs[tid] = g_acs[base + tid];
    dts[tid] = g_dt[base + tid];
    __syncthreads();

    float a_t = acs[tid];
    int bcq = b * NCHUNK + c;
    int i0 = (tid / 8) * 8;   // t-rows
    int j0 = (tid % 8) * 8;   // p-cols
    float acc[8][8];
#pragma unroll
    for (int i = 0; i < 8; i++)
#pragma unroll
        for (int j = 0; j < 8; j++) acc[i][j] = 0.f;

    for (int s0 = 0; s0 < CHUNK; s0 += 32) {
        // fill M^T column (thread owns t = tid)
        for (int s = 0; s < 32; s++) {
            int sg = s0 + s;
            float m = 0.f;
            if (sg <= tid)
                m = g_GT[(size_t)(bcq * CHUNK + sg) * CHUNK + tid] * expf(a_t - acs[sg]);
            Ms[s][tid] = m;
        }
        // fill dt-weighted x tile
        for (int idx = tid; idx < 32 * 64; idx += 256) {
            int s = idx >> 6, p = idx & 63;
            int sg = s0 + s;
            Xs[s][p] = dts[sg] *
                g_xbc[(size_t)(b * SEQ + c * CHUNK + sg) * CONV_DIM + h * HEAD_DIM + p];
        }
        __syncthreads();
        for (int s = 0; s < 32; s++) {
            float4 a0 = *(const float4*)&Ms[s][i0];
            float4 a1 = *(const float4*)&Ms[s][i0 + 4];
            float4 b0 = *(const float4*)&Xs[s][j0];
            float4 b1 = *(const float4*)&Xs[s][j0 + 4];
            float a[8] = {a0.x, a0.y, a0.z, a0.w, a1.x, a1.y, a1.z, a1.w};
            float bb[8] = {b0.x, b0.y, b0.z, b0.w, b1.x, b1.y, b1.z, b1.w};
#pragma unroll
            for (int i = 0; i < 8; i++)
#pragma unroll
                for (int j = 0; j < 8; j++) acc[i][j] += a[i] * bb[j];
        }
        __syncthreads();
    }
#pragma unroll
    for (int i = 0; i < 8; i++) {
        int t = i0 + i;
        float* yp = &g_y[(size_t)(b * SEQ + c * CHUNK + t) * D_INNER + h * HEAD_DIM + j0];
        *(float4*)yp = make_float4(acc[i][0], acc[i][1], acc[i][2], acc[i][3]);
        *(float4*)(yp + 4) = make_float4(acc[i][4], acc[i][5], acc[i][6], acc[i][7]);
    }
}

// ---------------- S[p,n] = sum_t B[t,n]*exp(acs_last - acs[t])*dt[t]*x[t,p] ----------------
__global__ __launch_bounds__(256) void states_kernel() {
    int c = blockIdx.x, h = blockIdx.y, b = blockIdx.z;
    int tid = threadIdx.x;
    __shared__ float acs[CHUNK], dts[CHUNK], wts[CHUNK];
    __shared__ __align__(16) float wxs[32][68];    // [t][p]
    __shared__ __align__(16) float Bsh[32][132];   // [t][n]
    int base = ((b * NHEADS + h) * NCHUNK + c) * CHUNK;
    acs[tid] = g_acs[base + tid];
    dts[tid] = g_dt[base + tid];
    __syncthreads();
    float alast = acs[CHUNK - 1];
    wts[tid] = expf(alast - acs[tid]) * dts[tid];
    __syncthreads();

    int p0 = (tid / 16) * 4, n0 = (tid % 16) * 8;
    float acc[4][8];
#pragma unroll
    for (int i = 0; i < 4; i++)
#pragma unroll
        for (int j = 0; j < 8; j++) acc[i][j] = 0.f;

    for (int t0 = 0; t0 < CHUNK; t0 += 32) {
        for (int idx = tid; idx < 32 * 64; idx += 256) {
            int tt = idx >> 6, p = idx & 63;
            int tg = t0 + tt;
            wxs[tt][p] = wts[tg] *
                g_xbc[(size_t)(b * SEQ + c * CHUNK + tg) * CONV_DIM + h * HEAD_DIM + p];
        }
        for (int idx = tid; idx < 32 * 128; idx += 256) {
            int tt = idx >> 7, n = idx & 127;
            Bsh[tt][n] = g_xbc[(size_t)(b * SEQ + c * CHUNK + t0 + tt) * CONV_DIM + 4096 + n];
        }
        __syncthreads();
        for (int t = 0; t < 32; t++) {
            float4 a = *(const float4*)&wxs[t][p0];
            float4 b0 = *(const float4*)&Bsh[t][n0];
            float4 b1 = *(const float4*)&Bsh[t][n0 + 4];
            float av[4] = {a.x, a.y, a.z, a.w};
            float bv[8] = {b0.x, b0.y, b0.z, b0.w, b1.x, b1.y, b1.z, b1.w};
#pragma unroll
            for (int i = 0; i < 4; i++)
#pragma unroll
                for (int j = 0; j < 8; j++) acc[i][j] += av[i] * bv[j];
        }
        __syncthreads();
    }
    int sbase = ((b * NCHUNK + c) * NHEADS + h) * HEAD_DIM;
#pragma unroll
    for (int i = 0; i < 4; i++) {
        float* sp = &g_S[(size_t)(sbase + p0 + i) * D_STATE + n0];
        *(float4*)sp = make_float4(acc[i][0], acc[i][1], acc[i][2], acc[i][3]);
        *(float4*)(sp + 4) = make_float4(acc[i][4], acc[i][5], acc[i][6], acc[i][7]);
    }
}

// ---------------- inter-chunk recurrence: P[c] = entering state of chunk c ----------------
__global__ void recur_kernel() {
    int idx = blockIdx.x * 256 + threadIdx.x;   // over BATCH*NHEADS*HEAD_DIM*D_STATE
    int n = idx & 127;
    int p = (idx >> 7) & 63;
    int h = (idx >> 13) & 63;
    int b = idx >> 19;
    float acc = 0.f;
#pragma unroll
    for (int c = 0; c < NCHUNK; c++) {
        size_t off = (size_t)(((b * NCHUNK + c) * NHEADS + h) * HEAD_DIM + p) * D_STATE + n;
        g_P[off] = acc;
        acc = acc * expf(g_ctot[(b * NHEADS + h) * NCHUNK + c]) + g_S[off];
    }
}

// ---------------- Y += exp(acs[t]) * (C @ P^T) + x*D  ----------------
__global__ __launch_bounds__(256) void yoff_kernel(const float* __restrict__ Dskip) {
    int c = blockIdx.x, h = blockIdx.y, b = blockIdx.z;
    int tid = threadIdx.x;
    __shared__ float acs[CHUNK];
    __shared__ __align__(16) float Cs[32][260];   // [n][t]
    __shared__ __align__(16) float Ps[32][68];    // [n][p]
    int base = ((b * NHEADS + h) * NCHUNK + c) * CHUNK;
    acs[tid] = g_acs[base + tid];
    __syncthreads();

    int i0 = (tid / 8) * 8;   // t
    int j0 = (tid % 8) * 8;   // p
    int pbase = ((b * NCHUNK + c) * NHEADS + h) * HEAD_DIM;
    float acc[8][8];
#pragma unroll
    for (int i = 0; i < 8; i++)
#pragma unroll
        for (int j = 0; j < 8; j++) acc[i][j] = 0.f;

    for (int n0 = 0; n0 < D_STATE; n0 += 32) {
        for (int idx = tid; idx < 32 * 256; idx += 256) {
            int nt = idx & 31, t = idx >> 5;
            Cs[nt][t] = g_xbc[(size_t)(b * SEQ + c * CHUNK + t) * CONV_DIM + 4224 + n0 + nt];
        }
        for (int idx = tid; idx < 32 * 64; idx += 256) {
            int nt = idx & 31, p = idx >> 5;
            Ps[nt][p] = g_P[(size_t)(pbase + p) * D_STATE + n0 + nt];
        }
        __syncthreads();
        for (int n = 0; n < 32; n++) {
            float4 a0 = *(const float4*)&Cs[n][i0];
            float4 a1 = *(const float4*)&Cs[n][i0 + 4];
            float4 b0 = *(const float4*)&Ps[n][j0];
            float4 b1 = *(const float4*)&Ps[n][j0 + 4];
            float a[8] = {a0.x, a0.y, a0.z, a0.w, a1.x, a1.y, a1.z, a1.w};
            float bb[8] = {b0.x, b0.y, b0.z, b0.w, b1.x, b1.y, b1.z, b1.w};
#pragma unroll
            for (int i = 0; i < 8; i++)
#pragma unroll
                for (int j = 0; j < 8; j++) acc[i][j] += a[i] * bb[j];
        }
        __syncthreads();
    }
    float Dh = Dskip[h];
#pragma unroll
    for (int i = 0; i < 8; i++) {
        int t = i0 + i;
        float e = expf(acs[t]);
        size_t ybase = (size_t)(b * SEQ + c * CHUNK + t) * D_INNER + h * HEAD_DIM + j0;
        size_t xbase = (size_t)(b * SEQ + c * CHUNK + t) * CONV_DIM + h * HEAD_DIM + j0;
        float4 y0 = *(float4*)&g_y[ybase];
        float4 y1 = *(float4*)&g_y[ybase + 4];
        float4 x0 = *(const float4*)&g_xbc[xbase];
        float4 x1 = *(const float4*)&g_xbc[xbase + 4];
        y0.x += acc[i][0] * e + x0.x * Dh;  y0.y += acc[i][1] * e + x0.y * Dh;
        y0.z += acc[i][2] * e + x0.z * Dh;  y0.w += acc[i][3] * e + x0.w * Dh;
        y1.x += acc[i][4] * e + x1.x * Dh;  y1.y += acc[i][5] * e + x1.y * Dh;
        y1.z += acc[i][6] * e + x1.z * Dh;  y1.w += acc[i][7] * e + x1.w * Dh;
        *(float4*)&g_y[ybase] = y0;
        *(float4*)&g_y[ybase + 4] = y1;
    }
}

// ---------------- gated RMSNorm: xn = (y*silu(z)) * rsqrt(mean+eps) * w ----------------
__global__ __launch_bounds__(256) void norm_kernel(const float* __restrict__ nw) {
    int tok = blockIdx.x;
    int tid = threadIdx.x;
    __shared__ float v[D_INNER];
    __shared__ float red[256];
    float s = 0.f;
#pragma unroll
    for (int k = 0; k < 16; k++) {
        int d = tid + k * 256;
        float yv = g_y[(size_t)tok * D_INNER + d];
        float zv = g_zxbcdt[(size_t)tok * D_IN_PROJ + d];
        float x = yv * (zv / (1.f + expf(-zv)));
        v[d] = x;
        s += x * x;
    }
    red[tid] = s;
    __syncthreads();
    for (int off = 128; off > 0; off >>= 1) {
        if (tid < off) red[tid] += red[tid + off];
        __syncthreads();
    }
    float scale = rsqrtf(red[0] / (float)D_INNER + 1e-5f);
#pragma unroll
    for (int k = 0; k < 16; k++) {
        int d = tid + k * 256;
        g_xn[(size_t)tok * D_INNER + d] = v[d] * scale * nw[d];
    }
}

// ---------------- launch ----------------
extern "C" void kernel_launch(void* const* d_in, const int* in_sizes, int n_in,
                              void* d_out, int out_size) {
    const float* hidden  = (const float*)d_in[0];
    const float* W_in    = (const float*)d_in[1];
    const float* conv_w  = (const float*)d_in[2];
    const float* conv_b  = (const float*)d_in[3];
    const float* A       = (const float*)d_in[4];
    const float* Dsk     = (const float*)d_in[5];
    const float* dt_bias = (const float*)d_in[6];
    const float* norm_w  = (const float*)d_in[7];
    const float* W_out   = (const float*)d_in[8];
    float* out = (float*)d_out;

    void* p;
    cudaGetSymbolAddress(&p, g_zxbcdt); float* zx = (float*)p;
    cudaGetSymbolAddress(&p, g_xn);     float* xn = (float*)p;

    // 1. in_proj (tf32 tensor cores)
    tf32gemm<<<dim3((D_IN_PROJ + 127) / 128, NTOK / 128), 256>>>(hidden, W_in, zx,
                                                                 NTOK, D_IN_PROJ, D_MODEL);
    // 2. conv + silu
    conv_kernel<<<(NTOK * CONV_DIM + 255) / 256, 256>>>(conv_w, conv_b);
    // 3. dt softplus + dA cumsum
    dt_scan_kernel<<<dim3(NCHUNK, NHEADS, BATCH), CHUNK>>>(dt_bias, A);
    // 4. G = C B^T (head-independent)
    gmat_kernel<<<dim3(4, 4, BATCH * NCHUNK), 256>>>();
    // 5. Y_diag
    ydiag_kernel<<<dim3(NCHUNK, NHEADS, BATCH), 256>>>();
    // 6. chunk states
    states_kernel<<<dim3(NCHUNK, NHEADS, BATCH), 256>>>();
    // 7. recurrence
    recur_kernel<<<(BATCH * NHEADS * HEAD_DIM * D_STATE) / 256, 256>>>();
    // 8. Y_off + D skip
    yoff_kernel<<<dim3(NCHUNK, NHEADS, BATCH), 256>>>(Dsk);
    // 9. gated rmsnorm
    norm_kernel<<<NTOK, 256>>>(norm_w);
    // 10. out_proj (tf32 tensor cores)
    tf32gemm<<<dim3(D_MODEL / 128, NTOK / 128), 256>>>(xn, W_out, out,
                                                       NTOK, D_MODEL, D_INNER);
}

// round 4
// speedup vs baseline: 2.5465x; 1.2622x over previous
#include <cuda_runtime.h>
#include <cstdint>
#include <math.h>

#define D_MODEL   2048
#define D_INNER   4096
#define NHEADS    64
#define HEAD_DIM  64
#define D_STATE   128
#define CHUNK     256
#define CONV_DIM  4352            // D_INNER + 2*D_STATE
#define D_IN_PROJ 8512            // 2*D_INNER + 2*D_STATE + NHEADS
#define BATCH     2
#define SEQ       2048
#define NTOK      (BATCH*SEQ)     // 4096
#define NCHUNK    (SEQ/CHUNK)     // 8

// ---------------- scratch (device globals: no allocation allowed) ----------------
__device__ float g_zxbcdt[NTOK * D_IN_PROJ];
__device__ float g_xbc[NTOK * CONV_DIM];
__device__ float g_dt [BATCH*NHEADS*NCHUNK*CHUNK];
__device__ float g_acs[BATCH*NHEADS*NCHUNK*CHUNK];
__device__ float g_ctot[BATCH*NHEADS*NCHUNK];
__device__ float g_GT[BATCH*NCHUNK*CHUNK*CHUNK];
__device__ float g_S [BATCH*NCHUNK*NHEADS*HEAD_DIM*D_STATE];
__device__ float g_P [BATCH*NCHUNK*NHEADS*HEAD_DIM*D_STATE];
__device__ float g_y [NTOK*D_INNER];
__device__ float g_xn[NTOK*D_INNER];                 // tf32-pre-rounded normed activations
__device__ float g_ha[NTOK*D_MODEL];                 // tf32-pre-rounded hidden
__device__ float g_wi[D_MODEL*D_IN_PROJ];            // tf32-pre-rounded W_in
__device__ float g_wo[D_INNER*D_MODEL];              // tf32-pre-rounded W_out

// ---------------- tf32 helpers ----------------
__device__ __forceinline__ uint32_t f2tf32(float x) {
    uint32_t r;
    asm("cvt.rna.tf32.f32 %0, %1;" : "=r"(r) : "f"(x));
    return r;
}

__device__ __forceinline__ void mma_tf32(float c[4],
                                         uint32_t a0, uint32_t a1, uint32_t a2, uint32_t a3,
                                         uint32_t b0, uint32_t b1) {
    asm volatile(
        "mma.sync.aligned.m16n8k8.row.col.f32.tf32.tf32.f32 "
        "{%0,%1,%2,%3},{%4,%5,%6,%7},{%8,%9},{%0,%1,%2,%3};"
        : "+f"(c[0]), "+f"(c[1]), "+f"(c[2]), "+f"(c[3])
        : "r"(a0), "r"(a1), "r"(a2), "r"(a3), "r"(b0), "r"(b1));
}

__device__ __forceinline__ void cpasync16(uint32_t dst, const void* src, int srcbytes) {
    asm volatile("cp.async.ca.shared.global [%0], [%1], 16, %2;"
                 :: "r"(dst), "l"(src), "r"(srcbytes));
}
__device__ __forceinline__ void cpasync_commit() {
    asm volatile("cp.async.commit_group;");
}
template <int N> __device__ __forceinline__ void cpasync_wait() {
    asm volatile("cp.async.wait_group %0;" :: "n"(N));
}

// ---------------- pre-round fp32 -> tf32 bits (elementwise) ----------------
__global__ void round_tf32_kernel(const float* __restrict__ in, float* __restrict__ out, int n) {
    int i = (blockIdx.x * blockDim.x + threadIdx.x) * 4;
    if (i >= n) return;
    float4 v = *(const float4*)(in + i);
    float4 o;
    o.x = __uint_as_float(f2tf32(v.x));
    o.y = __uint_as_float(f2tf32(v.y));
    o.z = __uint_as_float(f2tf32(v.z));
    o.w = __uint_as_float(f2tf32(v.w));
    *(float4*)(out + i) = o;
}

// ---------------- tf32 tensor-core GEMM (inputs pre-rounded to tf32 bits) ----------------
// C[M,N] = A[M,K] @ B[K,N]. 128x128 tile, BK=16, 256 threads (8 warps 2x4),
// warp tile 64x32 (m16n8k8). cp.async 2-stage pipeline, no in-loop conversion.
// Requires: M%128==0, K%16==0, N%4==0 (N edge bounds-checked).
__global__ __launch_bounds__(256, 2) void tf32gemm(const float* __restrict__ A,
                                                   const float* __restrict__ B,
                                                   float* __restrict__ C,
                                                   int M, int N, int K) {
    __shared__ uint32_t As[2][128][20];   // [stage][m][k], pad 20 (conflict-free)
    __shared__ uint32_t Bs[2][16][136];   // [stage][k][n], pad 136 (conflict-free)

    int tid = threadIdx.x;
    int lane = tid & 31, wid = tid >> 5;
    int wm = wid & 1, wn = wid >> 1;         // warp grid 2(m) x 4(n)
    int gID = lane >> 2, tig = lane & 3;
    int bx = blockIdx.x, by = blockIdx.y;

    uint32_t sA = (uint32_t)__cvta_generic_to_shared(&As[0][0][0]);
    uint32_t sB = (uint32_t)__cvta_generic_to_shared(&Bs[0][0][0]);
    const int A_STAGE = 128 * 20 * 4;        // bytes
    const int B_STAGE = 16 * 136 * 4;

    // loader mappings (each thread moves 2 float4 per tile per matrix)
    int a_i0 = tid, a_i1 = tid + 256;        // of 512 float4 (128 rows x 4 groups)
    int ar0 = a_i0 >> 2, ak0 = (a_i0 & 3) << 2;
    int ar1 = a_i1 >> 2, ak1 = (a_i1 & 3) << 2;
    const float* Arow0 = A + (size_t)(by * 128 + ar0) * K + ak0;
    const float* Arow1 = A + (size_t)(by * 128 + ar1) * K + ak1;

    int b_i0 = tid, b_i1 = tid + 256;        // of 512 float4 (16 k x 32 groups)
    int bk0 = b_i0 >> 5, bn0 = (b_i0 & 31) << 2;
    int bk1 = b_i1 >> 5, bn1 = (b_i1 & 31) << 2;
    int gc0 = bx * 128 + bn0, gc1 = bx * 128 + bn1;
    int sz0 = (gc0 < N) ? 16 : 0, sz1 = (gc1 < N) ? 16 : 0;
    const float* Bp0 = B + (size_t)bk0 * N + ((gc0 < N) ? gc0 : 0);
    const float* Bp1 = B + (size_t)bk1 * N + ((gc1 < N) ? gc1 : 0);

    float acc[4][4][4];
#pragma unroll
    for (int i = 0; i < 4; i++)
#pragma unroll
        for (int j = 0; j < 4; j++)
#pragma unroll
            for (int q = 0; q < 4; q++) acc[i][j][q] = 0.f;

    int ntiles = K >> 4;

    // prologue: stage 0
    cpasync16(sA + 0 * A_STAGE + (ar0 * 20 + ak0) * 4, Arow0, 16);
    cpasync16(sA + 0 * A_STAGE + (ar1 * 20 + ak1) * 4, Arow1, 16);
    cpasync16(sB + 0 * B_STAGE + (bk0 * 136 + bn0) * 4, Bp0, sz0);
    cpasync16(sB + 0 * B_STAGE + (bk1 * 136 + bn1) * 4, Bp1, sz1);
    cpasync_commit();

    for (int kt = 0; kt < ntiles; kt++) {
        int cur = kt & 1;
        bool more = (kt + 1 < ntiles);
        if (more) {
            int nxt = cur ^ 1;
            int k0 = (kt + 1) << 4;
            cpasync16(sA + nxt * A_STAGE + (ar0 * 20 + ak0) * 4, Arow0 + k0, 16);
            cpasync16(sA + nxt * A_STAGE + (ar1 * 20 + ak1) * 4, Arow1 + k0, 16);
            cpasync16(sB + nxt * B_STAGE + (bk0 * 136 + bn0) * 4, Bp0 + (size_t)k0 * N, sz0);
            cpasync16(sB + nxt * B_STAGE + (bk1 * 136 + bn1) * 4, Bp1 + (size_t)k0 * N, sz1);
            cpasync_commit();
            cpasync_wait<1>();
        } else {
            cpasync_wait<0>();
        }
        __syncthreads();

#pragma unroll
        for (int kk = 0; kk < 16; kk += 8) {
            uint32_t af[4][4], bf[4][2];
#pragma unroll
            for (int im = 0; im < 4; im++) {
                int row = wm * 64 + im * 16 + gID;
                af[im][0] = As[cur][row][kk + tig];
                af[im][1] = As[cur][row + 8][kk + tig];
                af[im][2] = As[cur][row][kk + 4 + tig];
                af[im][3] = As[cur][row + 8][kk + 4 + tig];
            }
#pragma unroll
            for (int in_ = 0; in_ < 4; in_++) {
                int col = wn * 32 + in_ * 8 + gID;
                bf[in_][0] = Bs[cur][kk + tig][col];
                bf[in_][1] = Bs[cur][kk + 4 + tig][col];
            }
#pragma unroll
            for (int im = 0; im < 4; im++)
#pragma unroll
                for (int in_ = 0; in_ < 4; in_++)
                    mma_tf32(acc[im][in_], af[im][0], af[im][1], af[im][2], af[im][3],
                             bf[in_][0], bf[in_][1]);
        }
        __syncthreads();
    }

    // epilogue
#pragma unroll
    for (int im = 0; im < 4; im++) {
#pragma unroll
        for (int in_ = 0; in_ < 4; in_++) {
            int r = by * 128 + wm * 64 + im * 16 + gID;
            int cc = bx * 128 + wn * 32 + in_ * 8 + 2 * tig;
            if (cc < N) {
                float2 v0 = make_float2(acc[im][in_][0], acc[im][in_][1]);
                float2 v1 = make_float2(acc[im][in_][2], acc[im][in_][3]);
                *(float2*)&C[(size_t)r * N + cc] = v0;
                *(float2*)&C[(size_t)(r + 8) * N + cc] = v1;
            }
        }
    }
}

// ---------------- causal conv1d (K=4) + SiLU over xbc channels ----------------
__global__ void conv_kernel(const float* __restrict__ w, const float* __restrict__ bias) {
    int idx = blockIdx.x * blockDim.x + threadIdx.x;
    if (idx >= NTOK * CONV_DIM) return;
    int c = idx % CONV_DIM;
    int tok = idx / CONV_DIM;
    int b = tok / SEQ, t = tok % SEQ;
    float acc = bias[c];
#pragma unroll
    for (int k = 0; k < 4; k++) {
        int tp = t - 3 + k;
        if (tp >= 0)
            acc += g_zxbcdt[(size_t)(b * SEQ + tp) * D_IN_PROJ + D_INNER + c] * w[c * 4 + k];
    }
    g_xbc[idx] = acc / (1.f + expf(-acc));   // silu
}

// ---------------- dt = softplus(raw + bias); dA = dt*A; per-chunk inclusive cumsum ----------------
__global__ void dt_scan_kernel(const float* __restrict__ dt_bias, const float* __restrict__ A) {
    int c = blockIdx.x, h = blockIdx.y, b = blockIdx.z;
    int t = threadIdx.x;  // 0..255
    int l = c * CHUNK + t;
    float raw = g_zxbcdt[(size_t)(b * SEQ + l) * D_IN_PROJ + (D_INNER + CONV_DIM) + h] + dt_bias[h];
    float dtv = (raw > 20.f) ? raw : log1pf(expf(raw));
    int base = ((b * NHEADS + h) * NCHUNK + c) * CHUNK;
    g_dt[base + t] = dtv;
    __shared__ float sb[CHUNK];
    sb[t] = dtv * A[h];
    __syncthreads();
    for (int off = 1; off < CHUNK; off <<= 1) {
        float v = (t >= off) ? sb[t - off] : 0.f;
        __syncthreads();
        sb[t] += v;
        __syncthreads();
    }
    g_acs[base + t] = sb[t];
    if (t == CHUNK - 1) g_ctot[(b * NHEADS + h) * NCHUNK + c] = sb[t];
}

// ---------------- G^T[bc][s][t] = sum_n C[t,n]*B[s,n]  (head-independent, NGROUPS=1) ----------------
__global__ __launch_bounds__(256) void gmat_kernel() {
    int bc = blockIdx.z;            // 0..15
    int b = bc >> 3, c = bc & 7;
    int s0 = blockIdx.x * 64, t0 = blockIdx.y * 64;
    __shared__ __align__(16) float Ct[64][65];
    __shared__ __align__(16) float Bt[64][65];
    int tid = threadIdx.x;
    int ti = (tid / 16) * 4, sj = (tid % 16) * 4;
    float acc[4][4];
#pragma unroll
    for (int i = 0; i < 4; i++)
#pragma unroll
        for (int j = 0; j < 4; j++) acc[i][j] = 0.f;

    for (int k0 = 0; k0 < D_STATE; k0 += 64) {
        for (int idx = tid; idx < 64 * 64; idx += 256) {
            int r = idx >> 6, kk = idx & 63;
            Ct[r][kk] = g_xbc[(size_t)(b * SEQ + c * CHUNK + t0 + r) * CONV_DIM + 4224 + k0 + kk];
            Bt[r][kk] = g_xbc[(size_t)(b * SEQ + c * CHUNK + s0 + r) * CONV_DIM + 4096 + k0 + kk];
        }
        __syncthreads();
        for (int k = 0; k < 64; k++) {
            float a[4], bb[4];
#pragma unroll
            for (int i = 0; i < 4; i++) { a[i] = Ct[ti + i][k]; bb[i] = Bt[sj + i][k]; }
#pragma unroll
            for (int i = 0; i < 4; i++)
#pragma unroll
                for (int j = 0; j < 4; j++) acc[i][j] += a[i] * bb[j];
        }
        __syncthreads();
    }
#pragma unroll
    for (int j = 0; j < 4; j++)
#pragma unroll
        for (int i = 0; i < 4; i++)
            g_GT[(size_t)(bc * CHUNK + s0 + sj + j) * CHUNK + t0 + ti + i] = acc[i][j];
}

// ---------------- Y_diag[t,p] = sum_s G[t,s]*exp(acs[t]-acs[s])*dt[s]*x[s,p] ----------------
__global__ __launch_bounds__(256) void ydiag_kernel() {
    int c = blockIdx.x, h = blockIdx.y, b = blockIdx.z;
    int tid = threadIdx.x;
    __shared__ float acs[CHUNK];
    __shared__ float dts[CHUNK];
    __shared__ __align__(16) float Ms[32][260];   // M^T: [s][t]
    __shared__ __align__(16) float Xs[32][68];    // dt-weighted x: [s][p]
    int base = ((b * NHEADS + h) * NCHUNK + c) * CHUNK;
    acs[tid] = g_acs[base + tid];
    dts[tid] = g_dt[base + tid];
    __syncthreads();

    float a_t = acs[tid];
    int bcq = b * NCHUNK + c;
    int i0 = (tid / 8) * 8;   // t-rows
    int j0 = (tid % 8) * 8;   // p-cols
    float acc[8][8];
#pragma unroll
    for (int i = 0; i < 8; i++)
#pragma unroll
        for (int j = 0; j < 8; j++) acc[i][j] = 0.f;

    for (int s0 = 0; s0 < CHUNK; s0 += 32) {
        for (int s = 0; s < 32; s++) {
            int sg = s0 + s;
            float m = 0.f;
            if (sg <= tid)
                m = g_GT[(size_t)(bcq * CHUNK + sg) * CHUNK + tid] * expf(a_t - acs[sg]);
            Ms[s][tid] = m;
        }
        for (int idx = tid; idx < 32 * 64; idx += 256) {
            int s = idx >> 6, p = idx & 63;
            int sg = s0 + s;
            Xs[s][p] = dts[sg] *
                g_xbc[(size_t)(b * SEQ + c * CHUNK + sg) * CONV_DIM + h * HEAD_DIM + p];
        }
        __syncthreads();
        for (int s = 0; s < 32; s++) {
            float4 a0 = *(const float4*)&Ms[s][i0];
            float4 a1 = *(const float4*)&Ms[s][i0 + 4];
            float4 b0 = *(const float4*)&Xs[s][j0];
            float4 b1 = *(const float4*)&Xs[s][j0 + 4];
            float a[8] = {a0.x, a0.y, a0.z, a0.w, a1.x, a1.y, a1.z, a1.w};
            float bb[8] = {b0.x, b0.y, b0.z, b0.w, b1.x, b1.y, b1.z, b1.w};
#pragma unroll
            for (int i = 0; i < 8; i++)
#pragma unroll
                for (int j = 0; j < 8; j++) acc[i][j] += a[i] * bb[j];
        }
        __syncthreads();
    }
#pragma unroll
    for (int i = 0; i < 8; i++) {
        int t = i0 + i;
        float* yp = &g_y[(size_t)(b * SEQ + c * CHUNK + t) * D_INNER + h * HEAD_DIM + j0];
        *(float4*)yp = make_float4(acc[i][0], acc[i][1], acc[i][2], acc[i][3]);
        *(float4*)(yp + 4) = make_float4(acc[i][4], acc[i][5], acc[i][6], acc[i][7]);
    }
}

// ---------------- S[p,n] = sum_t B[t,n]*exp(acs_last - acs[t])*dt[t]*x[t,p] ----------------
__global__ __launch_bounds__(256) void states_kernel() {
    int c = blockIdx.x, h = blockIdx.y, b = blockIdx.z;
    int tid = threadIdx.x;
    __shared__ float acs[CHUNK], dts[CHUNK], wts[CHUNK];
    __shared__ __align__(16) float wxs[32][68];    // [t][p]
    __shared__ __align__(16) float Bsh[32][132];   // [t][n]
    int base = ((b * NHEADS + h) * NCHUNK + c) * CHUNK;
    acs[tid] = g_acs[base + tid];
    dts[tid] = g_dt[base + tid];
    __syncthreads();
    float alast = acs[CHUNK - 1];
    wts[tid] = expf(alast - acs[tid]) * dts[tid];
    __syncthreads();

    int p0 = (tid / 16) * 4, n0 = (tid % 16) * 8;
    float acc[4][8];
#pragma unroll
    for (int i = 0; i < 4; i++)
#pragma unroll
        for (int j = 0; j < 8; j++) acc[i][j] = 0.f;

    for (int t0 = 0; t0 < CHUNK; t0 += 32) {
        for (int idx = tid; idx < 32 * 64; idx += 256) {
            int tt = idx >> 6, p = idx & 63;
            int tg = t0 + tt;
            wxs[tt][p] = wts[tg] *
                g_xbc[(size_t)(b * SEQ + c * CHUNK + tg) * CONV_DIM + h * HEAD_DIM + p];
        }
        for (int idx = tid; idx < 32 * 128; idx += 256) {
            int tt = idx >> 7, n = idx & 127;
            Bsh[tt][n] = g_xbc[(size_t)(b * SEQ + c * CHUNK + t0 + tt) * CONV_DIM + 4096 + n];
        }
        __syncthreads();
        for (int t = 0; t < 32; t++) {
            float4 a = *(const float4*)&wxs[t][p0];
            float4 b0 = *(const float4*)&Bsh[t][n0];
            float4 b1 = *(const float4*)&Bsh[t][n0 + 4];
            float av[4] = {a.x, a.y, a.z, a.w};
            float bv[8] = {b0.x, b0.y, b0.z, b0.w, b1.x, b1.y, b1.z, b1.w};
#pragma unroll
            for (int i = 0; i < 4; i++)
#pragma unroll
                for (int j = 0; j < 8; j++) acc[i][j] += av[i] * bv[j];
        }
        __syncthreads();
    }
    int sbase = ((b * NCHUNK + c) * NHEADS + h) * HEAD_DIM;
#pragma unroll
    for (int i = 0; i < 4; i++) {
        float* sp = &g_S[(size_t)(sbase + p0 + i) * D_STATE + n0];
        *(float4*)sp = make_float4(acc[i][0], acc[i][1], acc[i][2], acc[i][3]);
        *(float4*)(sp + 4) = make_float4(acc[i][4], acc[i][5], acc[i][6], acc[i][7]);
    }
}

// ---------------- inter-chunk recurrence ----------------
__global__ void recur_kernel() {
    int idx = blockIdx.x * 256 + threadIdx.x;
    int n = idx & 127;
    int p = (idx >> 7) & 63;
    int h = (idx >> 13) & 63;
    int b = idx >> 19;
    float acc = 0.f;
#pragma unroll
    for (int c = 0; c < NCHUNK; c++) {
        size_t off = (size_t)(((b * NCHUNK + c) * NHEADS + h) * HEAD_DIM + p) * D_STATE + n;
        g_P[off] = acc;
        acc = acc * expf(g_ctot[(b * NHEADS + h) * NCHUNK + c]) + g_S[off];
    }
}

// ---------------- Y += exp(acs[t]) * (C @ P^T) + x*D  ----------------
__global__ __launch_bounds__(256) void yoff_kernel(const float* __restrict__ Dskip) {
    int c = blockIdx.x, h = blockIdx.y, b = blockIdx.z;
    int tid = threadIdx.x;
    __shared__ float acs[CHUNK];
    __shared__ __align__(16) float Cs[32][260];   // [n][t]
    __shared__ __align__(16) float Ps[32][68];    // [n][p]
    int base = ((b * NHEADS + h) * NCHUNK + c) * CHUNK;
    acs[tid] = g_acs[base + tid];
    __syncthreads();

    int i0 = (tid / 8) * 8;   // t
    int j0 = (tid % 8) * 8;   // p
    int pbase = ((b * NCHUNK + c) * NHEADS + h) * HEAD_DIM;
    float acc[8][8];
#pragma unroll
    for (int i = 0; i < 8; i++)
#pragma unroll
        for (int j = 0; j < 8; j++) acc[i][j] = 0.f;

    for (int n0 = 0; n0 < D_STATE; n0 += 32) {
        for (int idx = tid; idx < 32 * 256; idx += 256) {
            int nt = idx & 31, t = idx >> 5;
            Cs[nt][t] = g_xbc[(size_t)(b * SEQ + c * CHUNK + t) * CONV_DIM + 4224 + n0 + nt];
        }
        for (int idx = tid; idx < 32 * 64; idx += 256) {
            int nt = idx & 31, p = idx >> 5;
            Ps[nt][p] = g_P[(size_t)(pbase + p) * D_STATE + n0 + nt];
        }
        __syncthreads();
        for (int n = 0; n < 32; n++) {
            float4 a0 = *(const float4*)&Cs[n][i0];
            float4 a1 = *(const float4*)&Cs[n][i0 + 4];
            float4 b0 = *(const float4*)&Ps[n][j0];
            float4 b1 = *(const float4*)&Ps[n][j0 + 4];
            float a[8] = {a0.x, a0.y, a0.z, a0.w, a1.x, a1.y, a1.z, a1.w};
            float bb[8] = {b0.x, b0.y, b0.z, b0.w, b1.x, b1.y, b1.z, b1.w};
#pragma unroll
            for (int i = 0; i < 8; i++)
#pragma unroll
                for (int j = 0; j < 8; j++) acc[i][j] += a[i] * bb[j];
        }
        __syncthreads();
    }
    float Dh = Dskip[h];
#pragma unroll
    for (int i = 0; i < 8; i++) {
        int t = i0 + i;
        float e = expf(acs[t]);
        size_t ybase = (size_t)(b * SEQ + c * CHUNK + t) * D_INNER + h * HEAD_DIM + j0;
        size_t xbase = (size_t)(b * SEQ + c * CHUNK + t) * CONV_DIM + h * HEAD_DIM + j0;
        float4 y0 = *(float4*)&g_y[ybase];
        float4 y1 = *(float4*)&g_y[ybase + 4];
        float4 x0 = *(const float4*)&g_xbc[xbase];
        float4 x1 = *(const float4*)&g_xbc[xbase + 4];
        y0.x += acc[i][0] * e + x0.x * Dh;  y0.y += acc[i][1] * e + x0.y * Dh;
        y0.z += acc[i][2] * e + x0.z * Dh;  y0.w += acc[i][3] * e + x0.w * Dh;
        y1.x += acc[i][4] * e + x1.x * Dh;  y1.y += acc[i][5] * e + x1.y * Dh;
        y1.z += acc[i][6] * e + x1.z * Dh;  y1.w += acc[i][7] * e + x1.w * Dh;
        *(float4*)&g_y[ybase] = y0;
        *(float4*)&g_y[ybase + 4] = y1;
    }
}

// ---------------- gated RMSNorm: xn = tf32round((y*silu(z)) * rsqrt(mean+eps) * w) ----------------
__global__ __launch_bounds__(256) void norm_kernel(const float* __restrict__ nw) {
    int tok = blockIdx.x;
    int tid = threadIdx.x;
    __shared__ float v[D_INNER];
    __shared__ float red[256];
    float s = 0.f;
#pragma unroll
    for (int k = 0; k < 16; k++) {
        int d = tid + k * 256;
        float yv = g_y[(size_t)tok * D_INNER + d];
        float zv = g_zxbcdt[(size_t)tok * D_IN_PROJ + d];
        float x = yv * (zv / (1.f + expf(-zv)));
        v[d] = x;
        s += x * x;
    }
    red[tid] = s;
    __syncthreads();
    for (int off = 128; off > 0; off >>= 1) {
        if (tid < off) red[tid] += red[tid + off];
        __syncthreads();
    }
    float scale = rsqrtf(red[0] / (float)D_INNER + 1e-5f);
#pragma unroll
    for (int k = 0; k < 16; k++) {
        int d = tid + k * 256;
        g_xn[(size_t)tok * D_INNER + d] = __uint_as_float(f2tf32(v[d] * scale * nw[d]));
    }
}

// ---------------- launch ----------------
extern "C" void kernel_launch(void* const* d_in, const int* in_sizes, int n_in,
                              void* d_out, int out_size) {
    const float* hidden  = (const float*)d_in[0];
    const float* W_in    = (const float*)d_in[1];
    const float* conv_w  = (const float*)d_in[2];
    const float* conv_b  = (const float*)d_in[3];
    const float* A       = (const float*)d_in[4];
    const float* Dsk     = (const float*)d_in[5];
    const float* dt_bias = (const float*)d_in[6];
    const float* norm_w  = (const float*)d_in[7];
    const float* W_out   = (const float*)d_in[8];
    float* out = (float*)d_out;

    void* p;
    cudaGetSymbolAddress(&p, g_zxbcdt); float* zx = (float*)p;
    cudaGetSymbolAddress(&p, g_xn);     float* xn = (float*)p;
    cudaGetSymbolAddress(&p, g_ha);     float* ha = (float*)p;
    cudaGetSymbolAddress(&p, g_wi);     float* wi = (float*)p;
    cudaGetSymbolAddress(&p, g_wo);     float* wo = (float*)p;

    // 0. pre-round GEMM operands to tf32 (hoists cvt out of GEMM inner loop)
    round_tf32_kernel<<<(NTOK * D_MODEL / 4 + 255) / 256, 256>>>(hidden, ha, NTOK * D_MODEL);
    round_tf32_kernel<<<(D_MODEL * D_IN_PROJ / 4 + 255) / 256, 256>>>(W_in, wi, D_MODEL * D_IN_PROJ);
    round_tf32_kernel<<<(D_INNER * D_MODEL / 4 + 255) / 256, 256>>>(W_out, wo, D_INNER * D_MODEL);

    // 1. in_proj
    tf32gemm<<<dim3((D_IN_PROJ + 127) / 128, NTOK / 128), 256>>>(ha, wi, zx,
                                                                 NTOK, D_IN_PROJ, D_MODEL);
    // 2. conv + silu
    conv_kernel<<<(NTOK * CONV_DIM + 255) / 256, 256>>>(conv_w, conv_b);
    // 3. dt softplus + dA cumsum
    dt_scan_kernel<<<dim3(NCHUNK, NHEADS, BATCH), CHUNK>>>(dt_bias, A);
    // 4. G = C B^T
    gmat_kernel<<<dim3(4, 4, BATCH * NCHUNK), 256>>>();
    // 5. Y_diag
    ydiag_kernel<<<dim3(NCHUNK, NHEADS, BATCH), 256>>>();
    // 6. chunk states
    states_kernel<<<dim3(NCHUNK, NHEADS, BATCH), 256>>>();
    // 7. recurrence
    recur_kernel<<<(BATCH * NHEADS * HEAD_DIM * D_STATE) / 256, 256>>>();
    // 8. Y_off + D skip
    yoff_kernel<<<dim3(NCHUNK, NHEADS, BATCH), 256>>>(Dsk);
    // 9. gated rmsnorm (emits tf32-rounded xn)
    norm_kernel<<<NTOK, 256>>>(norm_w);
    // 10. out_proj
    tf32gemm<<<dim3(D_MODEL / 128, NTOK / 128), 256>>>(xn, wo, out,
                                                       NTOK, D_MODEL, D_INNER);
}

// round 5
// speedup vs baseline: 2.8556x; 1.1214x over previous
#include <cuda_runtime.h>
#include <cstdint>
#include <math.h>

#define D_MODEL   2048
#define D_INNER   4096
#define NHEADS    64
#define HEAD_DIM  64
#define D_STATE   128
#define CHUNK     256
#define CONV_DIM  4352            // D_INNER + 2*D_STATE
#define D_IN_PROJ 8512            // 2*D_INNER + 2*D_STATE + NHEADS
#define BATCH     2
#define SEQ       2048
#define NTOK      (BATCH*SEQ)     // 4096
#define NCHUNK    (SEQ/CHUNK)     // 8

// ---------------- scratch (device globals: no allocation allowed) ----------------
__device__ float g_zxbcdt[NTOK * D_IN_PROJ];
__device__ float g_xbc[NTOK * CONV_DIM];
__device__ float g_dt [BATCH*NHEADS*NCHUNK*CHUNK];
__device__ float g_acs[BATCH*NHEADS*NCHUNK*CHUNK];
__device__ float g_ctot[BATCH*NHEADS*NCHUNK];
__device__ float g_GT[BATCH*NCHUNK*CHUNK*CHUNK];                   // [bc][s][t]
__device__ float g_S [BATCH*NCHUNK*NHEADS*D_STATE*HEAD_DIM];      // S^T: [bch][n][p]
__device__ float g_P [BATCH*NCHUNK*NHEADS*D_STATE*HEAD_DIM];      // P^T: [bch][n][p]
__device__ float g_y [NTOK*D_INNER];
__device__ float g_xn[NTOK*D_INNER];
__device__ float g_ha[NTOK*D_MODEL];
__device__ float g_wi[D_MODEL*D_IN_PROJ];
__device__ float g_wo[D_INNER*D_MODEL];

// ---------------- tf32 helpers ----------------
__device__ __forceinline__ uint32_t f2tf32(float x) {
    uint32_t r;
    asm("cvt.rna.tf32.f32 %0, %1;" : "=r"(r) : "f"(x));
    return r;
}

__device__ __forceinline__ void split_tf32(float x, float& hi, float& lo) {
    uint32_t h = f2tf32(x);
    hi = __uint_as_float(h);
    lo = __uint_as_float(f2tf32(x - __uint_as_float(h)));
}

__device__ __forceinline__ void mma_tf32(float c[4],
                                         uint32_t a0, uint32_t a1, uint32_t a2, uint32_t a3,
                                         uint32_t b0, uint32_t b1) {
    asm volatile(
        "mma.sync.aligned.m16n8k8.row.col.f32.tf32.tf32.f32 "
        "{%0,%1,%2,%3},{%4,%5,%6,%7},{%8,%9},{%0,%1,%2,%3};"
        : "+f"(c[0]), "+f"(c[1]), "+f"(c[2]), "+f"(c[3])
        : "r"(a0), "r"(a1), "r"(a2), "r"(a3), "r"(b0), "r"(b1));
}

// split-precision 3-mma: acc += (Ahi+Alo)*(Bhi+Blo) (drops lo*lo)
__device__ __forceinline__ void mma3(float c[4],
                                     const uint32_t ah[4], const uint32_t al[4],
                                     uint32_t bh0, uint32_t bh1, uint32_t bl0, uint32_t bl1) {
    mma_tf32(c, ah[0], ah[1], ah[2], ah[3], bh0, bh1);
    mma_tf32(c, al[0], al[1], al[2], al[3], bh0, bh1);
    mma_tf32(c, ah[0], ah[1], ah[2], ah[3], bl0, bl1);
}

__device__ __forceinline__ void cpasync16(uint32_t dst, const void* src, int srcbytes) {
    asm volatile("cp.async.ca.shared.global [%0], [%1], 16, %2;"
                 :: "r"(dst), "l"(src), "r"(srcbytes));
}
__device__ __forceinline__ void cpasync_commit() {
    asm volatile("cp.async.commit_group;");
}
template <int N> __device__ __forceinline__ void cpasync_wait() {
    asm volatile("cp.async.wait_group %0;" :: "n"(N));
}

// ---------------- pre-round fp32 -> tf32 bits (elementwise) ----------------
__global__ void round_tf32_kernel(const float* __restrict__ in, float* __restrict__ out, int n) {
    int i = (blockIdx.x * blockDim.x + threadIdx.x) * 4;
    if (i >= n) return;
    float4 v = *(const float4*)(in + i);
    float4 o;
    o.x = __uint_as_float(f2tf32(v.x));
    o.y = __uint_as_float(f2tf32(v.y));
    o.z = __uint_as_float(f2tf32(v.z));
    o.w = __uint_as_float(f2tf32(v.w));
    *(float4*)(out + i) = o;
}

// ---------------- tf32 tensor-core GEMM (inputs pre-rounded) ----------------
__global__ __launch_bounds__(256, 2) void tf32gemm(const float* __restrict__ A,
                                                   const float* __restrict__ B,
                                                   float* __restrict__ C,
                                                   int M, int N, int K) {
    __shared__ uint32_t As[2][128][20];
    __shared__ uint32_t Bs[2][16][136];

    int tid = threadIdx.x;
    int lane = tid & 31, wid = tid >> 5;
    int wm = wid & 1, wn = wid >> 1;
    int gID = lane >> 2, tig = lane & 3;
    int bx = blockIdx.x, by = blockIdx.y;

    uint32_t sA = (uint32_t)__cvta_generic_to_shared(&As[0][0][0]);
    uint32_t sB = (uint32_t)__cvta_generic_to_shared(&Bs[0][0][0]);
    const int A_STAGE = 128 * 20 * 4;
    const int B_STAGE = 16 * 136 * 4;

    int a_i0 = tid, a_i1 = tid + 256;
    int ar0 = a_i0 >> 2, ak0 = (a_i0 & 3) << 2;
    int ar1 = a_i1 >> 2, ak1 = (a_i1 & 3) << 2;
    const float* Arow0 = A + (size_t)(by * 128 + ar0) * K + ak0;
    const float* Arow1 = A + (size_t)(by * 128 + ar1) * K + ak1;

    int b_i0 = tid, b_i1 = tid + 256;
    int bk0 = b_i0 >> 5, bn0 = (b_i0 & 31) << 2;
    int bk1 = b_i1 >> 5, bn1 = (b_i1 & 31) << 2;
    int gc0 = bx * 128 + bn0, gc1 = bx * 128 + bn1;
    int sz0 = (gc0 < N) ? 16 : 0, sz1 = (gc1 < N) ? 16 : 0;
    const float* Bp0 = B + (size_t)bk0 * N + ((gc0 < N) ? gc0 : 0);
    const float* Bp1 = B + (size_t)bk1 * N + ((gc1 < N) ? gc1 : 0);

    float acc[4][4][4];
#pragma unroll
    for (int i = 0; i < 4; i++)
#pragma unroll
        for (int j = 0; j < 4; j++)
#pragma unroll
            for (int q = 0; q < 4; q++) acc[i][j][q] = 0.f;

    int ntiles = K >> 4;

    cpasync16(sA + 0 * A_STAGE + (ar0 * 20 + ak0) * 4, Arow0, 16);
    cpasync16(sA + 0 * A_STAGE + (ar1 * 20 + ak1) * 4, Arow1, 16);
    cpasync16(sB + 0 * B_STAGE + (bk0 * 136 + bn0) * 4, Bp0, sz0);
    cpasync16(sB + 0 * B_STAGE + (bk1 * 136 + bn1) * 4, Bp1, sz1);
    cpasync_commit();

    for (int kt = 0; kt < ntiles; kt++) {
        int cur = kt & 1;
        bool more = (kt + 1 < ntiles);
        if (more) {
            int nxt = cur ^ 1;
            int k0 = (kt + 1) << 4;
            cpasync16(sA + nxt * A_STAGE + (ar0 * 20 + ak0) * 4, Arow0 + k0, 16);
            cpasync16(sA + nxt * A_STAGE + (ar1 * 20 + ak1) * 4, Arow1 + k0, 16);
            cpasync16(sB + nxt * B_STAGE + (bk0 * 136 + bn0) * 4, Bp0 + (size_t)k0 * N, sz0);
            cpasync16(sB + nxt * B_STAGE + (bk1 * 136 + bn1) * 4, Bp1 + (size_t)k0 * N, sz1);
            cpasync_commit();
            cpasync_wait<1>();
        } else {
            cpasync_wait<0>();
        }
        __syncthreads();

#pragma unroll
        for (int kk = 0; kk < 16; kk += 8) {
            uint32_t af[4][4], bf[4][2];
#pragma unroll
            for (int im = 0; im < 4; im++) {
                int row = wm * 64 + im * 16 + gID;
                af[im][0] = As[cur][row][kk + tig];
                af[im][1] = As[cur][row + 8][kk + tig];
                af[im][2] = As[cur][row][kk + 4 + tig];
                af[im][3] = As[cur][row + 8][kk + 4 + tig];
            }
#pragma unroll
            for (int in_ = 0; in_ < 4; in_++) {
                int col = wn * 32 + in_ * 8 + gID;
                bf[in_][0] = Bs[cur][kk + tig][col];
                bf[in_][1] = Bs[cur][kk + 4 + tig][col];
            }
#pragma unroll
            for (int im = 0; im < 4; im++)
#pragma unroll
                for (int in_ = 0; in_ < 4; in_++)
                    mma_tf32(acc[im][in_], af[im][0], af[im][1], af[im][2], af[im][3],
                             bf[in_][0], bf[in_][1]);
        }
        __syncthreads();
    }

#pragma unroll
    for (int im = 0; im < 4; im++) {
#pragma unroll
        for (int in_ = 0; in_ < 4; in_++) {
            int r = by * 128 + wm * 64 + im * 16 + gID;
            int cc = bx * 128 + wn * 32 + in_ * 8 + 2 * tig;
            if (cc < N) {
                float2 v0 = make_float2(acc[im][in_][0], acc[im][in_][1]);
                float2 v1 = make_float2(acc[im][in_][2], acc[im][in_][3]);
                *(float2*)&C[(size_t)r * N + cc] = v0;
                *(float2*)&C[(size_t)(r + 8) * N + cc] = v1;
            }
        }
    }
}

// ---------------- causal conv1d (K=4) + SiLU ----------------
__global__ void conv_kernel(const float* __restrict__ w, const float* __restrict__ bias) {
    int idx = blockIdx.x * blockDim.x + threadIdx.x;
    if (idx >= NTOK * CONV_DIM) return;
    int c = idx % CONV_DIM;
    int tok = idx / CONV_DIM;
    int b = tok / SEQ, t = tok % SEQ;
    float acc = bias[c];
#pragma unroll
    for (int k = 0; k < 4; k++) {
        int tp = t - 3 + k;
        if (tp >= 0)
            acc += g_zxbcdt[(size_t)(b * SEQ + tp) * D_IN_PROJ + D_INNER + c] * w[c * 4 + k];
    }
    g_xbc[idx] = acc / (1.f + expf(-acc));
}

// ---------------- dt softplus + per-chunk dA cumsum ----------------
__global__ void dt_scan_kernel(const float* __restrict__ dt_bias, const float* __restrict__ A) {
    int c = blockIdx.x, h = blockIdx.y, b = blockIdx.z;
    int t = threadIdx.x;
    int l = c * CHUNK + t;
    float raw = g_zxbcdt[(size_t)(b * SEQ + l) * D_IN_PROJ + (D_INNER + CONV_DIM) + h] + dt_bias[h];
    float dtv = (raw > 20.f) ? raw : log1pf(expf(raw));
    int base = ((b * NHEADS + h) * NCHUNK + c) * CHUNK;
    g_dt[base + t] = dtv;
    __shared__ float sb[CHUNK];
    sb[t] = dtv * A[h];
    __syncthreads();
    for (int off = 1; off < CHUNK; off <<= 1) {
        float v = (t >= off) ? sb[t - off] : 0.f;
        __syncthreads();
        sb[t] += v;
        __syncthreads();
    }
    g_acs[base + t] = sb[t];
    if (t == CHUNK - 1) g_ctot[(b * NHEADS + h) * NCHUNK + c] = sb[t];
}

// ---------------- G^T[bc][s][t] = sum_n C[t,n]*B[s,n] ----------------
__global__ __launch_bounds__(256) void gmat_kernel() {
    int bc = blockIdx.z;
    int b = bc >> 3, c = bc & 7;
    int s0 = blockIdx.x * 64, t0 = blockIdx.y * 64;
    __shared__ __align__(16) float Ct[64][65];
    __shared__ __align__(16) float Bt[64][65];
    int tid = threadIdx.x;
    int ti = (tid / 16) * 4, sj = (tid % 16) * 4;
    float acc[4][4];
#pragma unroll
    for (int i = 0; i < 4; i++)
#pragma unroll
        for (int j = 0; j < 4; j++) acc[i][j] = 0.f;

    for (int k0 = 0; k0 < D_STATE; k0 += 64) {
        for (int idx = tid; idx < 64 * 64; idx += 256) {
            int r = idx >> 6, kk = idx & 63;
            Ct[r][kk] = g_xbc[(size_t)(b * SEQ + c * CHUNK + t0 + r) * CONV_DIM + 4224 + k0 + kk];
            Bt[r][kk] = g_xbc[(size_t)(b * SEQ + c * CHUNK + s0 + r) * CONV_DIM + 4096 + k0 + kk];
        }
        __syncthreads();
        for (int k = 0; k < 64; k++) {
            float a[4], bb[4];
#pragma unroll
            for (int i = 0; i < 4; i++) { a[i] = Ct[ti + i][k]; bb[i] = Bt[sj + i][k]; }
#pragma unroll
            for (int i = 0; i < 4; i++)
#pragma unroll
                for (int j = 0; j < 4; j++) acc[i][j] += a[i] * bb[j];
        }
        __syncthreads();
    }
#pragma unroll
    for (int j = 0; j < 4; j++)
#pragma unroll
        for (int i = 0; i < 4; i++)
            g_GT[(size_t)(bc * CHUNK + s0 + sj + j) * CHUNK + t0 + ti + i] = acc[i][j];
}

// ---------------- Y_diag: split-tf32 mma, M built in registers, causal skip ----------------
// Per (b,c,h): Y[t,p] = sum_s M[t,s]*(dt[s]*x[s,p]),  M = (s<=t)? G[t,s]*exp(acs_t-acs_s) : 0
__device__ __forceinline__ void mval_split(const float* __restrict__ GT, int s, int t,
                                           float e_t, float a_s, uint32_t& hi, uint32_t& lo) {
    float m = 0.f;
    if (s <= t) m = GT[(size_t)s * CHUNK + t] * __expf(e_t - a_s);
    hi = f2tf32(m);
    lo = f2tf32(m - __uint_as_float(hi));
}

__global__ __launch_bounds__(256) void ydiag_kernel() {
    int c = blockIdx.x, h = blockIdx.y, b = blockIdx.z;
    int tid = threadIdx.x, lane = tid & 31, wid = tid >> 5;
    int gID = lane >> 2, tig = lane & 3;
    __shared__ float acs[CHUNK], dts[CHUNK];
    __shared__ __align__(16) float Xhi[32][72], Xlo[32][72];
    int base = ((b * NHEADS + h) * NCHUNK + c) * CHUNK;
    acs[tid] = g_acs[base + tid];
    dts[tid] = g_dt[base + tid];
    __syncthreads();

    int wbase = wid * 32;
    const float* GT = g_GT + (size_t)(b * NCHUNK + c) * CHUNK * CHUNK;
    const float* xrow = g_xbc + (size_t)(b * SEQ + c * CHUNK) * CONV_DIM + h * HEAD_DIM;

    float e_t[2][2];
#pragma unroll
    for (int im = 0; im < 2; im++) {
        e_t[im][0] = acs[wbase + im * 16 + gID];
        e_t[im][1] = acs[wbase + im * 16 + 8 + gID];
    }

    float acc[2][8][4];
#pragma unroll
    for (int im = 0; im < 2; im++)
#pragma unroll
        for (int nt = 0; nt < 8; nt++)
#pragma unroll
            for (int q = 0; q < 4; q++) acc[im][nt][q] = 0.f;

    for (int s0 = 0; s0 < CHUNK; s0 += 32) {
        for (int i = tid; i < 32 * 64; i += 256) {
            int s = i >> 6, p = i & 63;
            float v = dts[s0 + s] * xrow[(size_t)(s0 + s) * CONV_DIM + p];
            split_tf32(v, Xhi[s][p], Xlo[s][p]);
        }
        __syncthreads();
        if (s0 <= wbase + 31) {
            for (int kk = 0; kk < 32; kk += 8) {
                if (s0 + kk > wbase + 31) break;
                int sa = s0 + kk + tig, sb = sa + 4;
                float aa = acs[sa], ab = acs[sb];
                uint32_t ahi[2][4], alo[2][4];
#pragma unroll
                for (int im = 0; im < 2; im++) {
                    int t0 = wbase + im * 16 + gID;
                    mval_split(GT, sa, t0,     e_t[im][0], aa, ahi[im][0], alo[im][0]);
                    mval_split(GT, sa, t0 + 8, e_t[im][1], aa, ahi[im][1], alo[im][1]);
                    mval_split(GT, sb, t0,     e_t[im][0], ab, ahi[im][2], alo[im][2]);
                    mval_split(GT, sb, t0 + 8, e_t[im][1], ab, ahi[im][3], alo[im][3]);
                }
#pragma unroll
                for (int nt = 0; nt < 8; nt++) {
                    int col = nt * 8 + gID;
                    uint32_t bh0 = __float_as_uint(Xhi[kk + tig][col]);
                    uint32_t bh1 = __float_as_uint(Xhi[kk + 4 + tig][col]);
                    uint32_t bl0 = __float_as_uint(Xlo[kk + tig][col]);
                    uint32_t bl1 = __float_as_uint(Xlo[kk + 4 + tig][col]);
#pragma unroll
                    for (int im = 0; im < 2; im++)
                        mma3(acc[im][nt], ahi[im], alo[im], bh0, bh1, bl0, bl1);
                }
            }
        }
        __syncthreads();
    }

    float* yrow = g_y + (size_t)(b * SEQ + c * CHUNK) * D_INNER + h * HEAD_DIM;
#pragma unroll
    for (int im = 0; im < 2; im++) {
        int t0 = wbase + im * 16 + gID;
#pragma unroll
        for (int nt = 0; nt < 8; nt++) {
            int col = nt * 8 + 2 * tig;
            *(float2*)&yrow[(size_t)t0 * D_INNER + col] =
                make_float2(acc[im][nt][0], acc[im][nt][1]);
            *(float2*)&yrow[(size_t)(t0 + 8) * D_INNER + col] =
                make_float2(acc[im][nt][2], acc[im][nt][3]);
        }
    }
}

// ---------------- states: S^T[n][p] = sum_t B[t,n]*wts[t]*x[t,p]  (split-tf32 mma) ----------------
__global__ __launch_bounds__(256) void states_kernel() {
    int c = blockIdx.x, h = blockIdx.y, b = blockIdx.z;
    int tid = threadIdx.x, lane = tid & 31, wid = tid >> 5;
    int gID = lane >> 2, tig = lane & 3;
    __shared__ float acs_s[CHUNK], wts[CHUNK];
    __shared__ __align__(16) float Ahi[16][136], Alo[16][136];
    __shared__ __align__(16) float Bh[16][72], Bl[16][72];
    int base = ((b * NHEADS + h) * NCHUNK + c) * CHUNK;
    acs_s[tid] = g_acs[base + tid];
    __syncthreads();
    float alast = acs_s[CHUNK - 1];
    wts[tid] = __expf(alast - acs_s[tid]) * g_dt[base + tid];

    const float* bsrc = g_xbc + (size_t)(b * SEQ + c * CHUNK) * CONV_DIM + 4096;
    const float* xrow = g_xbc + (size_t)(b * SEQ + c * CHUNK) * CONV_DIM + h * HEAD_DIM;

    float acc[8][4];
#pragma unroll
    for (int nt = 0; nt < 8; nt++)
#pragma unroll
        for (int q = 0; q < 4; q++) acc[nt][q] = 0.f;

    for (int t0 = 0; t0 < CHUNK; t0 += 16) {
        __syncthreads();
        for (int i = tid; i < 16 * 128; i += 256) {
            int t = i >> 7, n = i & 127;
            float v = bsrc[(size_t)(t0 + t) * CONV_DIM + n];
            split_tf32(v, Ahi[t][n], Alo[t][n]);
        }
        for (int i = tid; i < 16 * 64; i += 256) {
            int t = i >> 6, p = i & 63;
            float v = wts[t0 + t] * xrow[(size_t)(t0 + t) * CONV_DIM + p];
            split_tf32(v, Bh[t][p], Bl[t][p]);
        }
        __syncthreads();
#pragma unroll
        for (int kk = 0; kk < 16; kk += 8) {
            int row = wid * 16 + gID;
            uint32_t ah[4], al[4];
            ah[0] = __float_as_uint(Ahi[kk + tig][row]);
            ah[1] = __float_as_uint(Ahi[kk + tig][row + 8]);
            ah[2] = __float_as_uint(Ahi[kk + 4 + tig][row]);
            ah[3] = __float_as_uint(Ahi[kk + 4 + tig][row + 8]);
            al[0] = __float_as_uint(Alo[kk + tig][row]);
            al[1] = __float_as_uint(Alo[kk + tig][row + 8]);
            al[2] = __float_as_uint(Alo[kk + 4 + tig][row]);
            al[3] = __float_as_uint(Alo[kk + 4 + tig][row + 8]);
#pragma unroll
            for (int nt = 0; nt < 8; nt++) {
                int col = nt * 8 + gID;
                uint32_t bh0 = __float_as_uint(Bh[kk + tig][col]);
                uint32_t bh1 = __float_as_uint(Bh[kk + 4 + tig][col]);
                uint32_t bl0 = __float_as_uint(Bl[kk + tig][col]);
                uint32_t bl1 = __float_as_uint(Bl[kk + 4 + tig][col]);
                mma3(acc[nt], ah, al, bh0, bh1, bl0, bl1);
            }
        }
    }

    float* Sp = g_S + (size_t)((b * NCHUNK + c) * NHEADS + h) * D_STATE * HEAD_DIM;
    int n = wid * 16 + gID;
#pragma unroll
    for (int nt = 0; nt < 8; nt++) {
        int p = nt * 8 + 2 * tig;
        *(float2*)&Sp[n * HEAD_DIM + p] = make_float2(acc[nt][0], acc[nt][1]);
        *(float2*)&Sp[(n + 8) * HEAD_DIM + p] = make_float2(acc[nt][2], acc[nt][3]);
    }
}

// ---------------- inter-chunk recurrence (S^T/P^T layout [n][p]) ----------------
__global__ void recur_kernel() {
    int idx = blockIdx.x * 256 + threadIdx.x;
    int p = idx & 63;
    int n = (idx >> 6) & 127;
    int h = (idx >> 13) & 63;
    int b = idx >> 19;
    float acc = 0.f;
#pragma unroll
    for (int c = 0; c < NCHUNK; c++) {
        size_t off = (size_t)(((b * NCHUNK + c) * NHEADS + h) * D_STATE + n) * HEAD_DIM + p;
        g_P[off] = acc;
        acc = acc * __expf(g_ctot[(b * NHEADS + h) * NCHUNK + c]) + g_S[off];
    }
}

// ---------------- Y += exp(acs[t])*(C @ P) + x*D   (split-tf32 mma; 2 blocks per chunk) ----------------
__global__ __launch_bounds__(256) void yoff_kernel(const float* __restrict__ Dskip) {
    int cc = blockIdx.x;
    int c = cc >> 1, half = cc & 1;
    int h = blockIdx.y, b = blockIdx.z;
    int tid = threadIdx.x, lane = tid & 31, wid = tid >> 5;
    int gID = lane >> 2, tig = lane & 3;
    __shared__ float acs_s[CHUNK];
    __shared__ __align__(16) float Ahi[128][20], Alo[128][20];
    __shared__ __align__(16) float Bh[16][72], Bl[16][72];
    int base = ((b * NHEADS + h) * NCHUNK + c) * CHUNK;
    acs_s[tid] = g_acs[base + tid];

    const float* crow = g_xbc + (size_t)(b * SEQ + c * CHUNK + half * 128) * CONV_DIM + 4224;
    const float* Pp = g_P + (size_t)((b * NCHUNK + c) * NHEADS + h) * D_STATE * HEAD_DIM;

    float acc[8][4];
#pragma unroll
    for (int nt = 0; nt < 8; nt++)
#pragma unroll
        for (int q = 0; q < 4; q++) acc[nt][q] = 0.f;

    for (int n0 = 0; n0 < D_STATE; n0 += 16) {
        __syncthreads();
        for (int i = tid; i < 128 * 16; i += 256) {
            int t = i >> 4, n = i & 15;
            float v = crow[(size_t)t * CONV_DIM + n0 + n];
            split_tf32(v, Ahi[t][n], Alo[t][n]);
        }
        for (int i = tid; i < 16 * 64; i += 256) {
            int n = i >> 6, p = i & 63;
            float v = Pp[(n0 + n) * HEAD_DIM + p];
            split_tf32(v, Bh[n][p], Bl[n][p]);
        }
        __syncthreads();
#pragma unroll
        for (int kk = 0; kk < 16; kk += 8) {
            int row = wid * 16 + gID;
            uint32_t ah[4], al[4];
            ah[0] = __float_as_uint(Ahi[row][kk + tig]);
            ah[1] = __float_as_uint(Ahi[row + 8][kk + tig]);
            ah[2] = __float_as_uint(Ahi[row][kk + 4 + tig]);
            ah[3] = __float_as_uint(Ahi[row + 8][kk + 4 + tig]);
            al[0] = __float_as_uint(Alo[row][kk + tig]);
            al[1] = __float_as_uint(Alo[row + 8][kk + tig]);
            al[2] = __float_as_uint(Alo[row][kk + 4 + tig]);
            al[3] = __float_as_uint(Alo[row + 8][kk + 4 + tig]);
#pragma unroll
            for (int nt = 0; nt < 8; nt++) {
                int col = nt * 8 + gID;
                uint32_t bh0 = __float_as_uint(Bh[kk + tig][col]);
                uint32_t bh1 = __float_as_uint(Bh[kk + 4 + tig][col]);
                uint32_t bl0 = __float_as_uint(Bl[kk + tig][col]);
                uint32_t bl1 = __float_as_uint(Bl[kk + 4 + tig][col]);
                mma3(acc[nt], ah, al, bh0, bh1, bl0, bl1);
            }
        }
    }

    float Dh = Dskip[h];
    float* yrow = g_y + (size_t)(b * SEQ + c * CHUNK + half * 128) * D_INNER + h * HEAD_DIM;
    const float* xr = g_xbc + (size_t)(b * SEQ + c * CHUNK + half * 128) * CONV_DIM + h * HEAD_DIM;
    int r0 = wid * 16 + gID;
    float e0 = __expf(acs_s[half * 128 + r0]);
    float e1 = __expf(acs_s[half * 128 + r0 + 8]);
#pragma unroll
    for (int nt = 0; nt < 8; nt++) {
        int col = nt * 8 + 2 * tig;
        float2 y0 = *(float2*)&yrow[(size_t)r0 * D_INNER + col];
        float2 x0 = *(const float2*)&xr[(size_t)r0 * CONV_DIM + col];
        y0.x += acc[nt][0] * e0 + x0.x * Dh;
        y0.y += acc[nt][1] * e0 + x0.y * Dh;
        *(float2*)&yrow[(size_t)r0 * D_INNER + col] = y0;
        float2 y1 = *(float2*)&yrow[(size_t)(r0 + 8) * D_INNER + col];
        float2 x1 = *(const float2*)&xr[(size_t)(r0 + 8) * CONV_DIM + col];
        y1.x += acc[nt][2] * e1 + x1.x * Dh;
        y1.y += acc[nt][3] * e1 + x1.y * Dh;
        *(float2*)&yrow[(size_t)(r0 + 8) * D_INNER + col] = y1;
    }
}

// ---------------- gated RMSNorm (emits tf32-rounded xn) ----------------
__global__ __launch_bounds__(256) void norm_kernel(const float* __restrict__ nw) {
    int tok = blockIdx.x;
    int tid = threadIdx.x;
    __shared__ float v[D_INNER];
    __shared__ float red[256];
    float s = 0.f;
#pragma unroll
    for (int k = 0; k < 16; k++) {
        int d = tid + k * 256;
        float yv = g_y[(size_t)tok * D_INNER + d];
        float zv = g_zxbcdt[(size_t)tok * D_IN_PROJ + d];
        float x = yv * (zv / (1.f + expf(-zv)));
        v[d] = x;
        s += x * x;
    }
    red[tid] = s;
    __syncthreads();
    for (int off = 128; off > 0; off >>= 1) {
        if (tid < off) red[tid] += red[tid + off];
        __syncthreads();
    }
    float scale = rsqrtf(red[0] / (float)D_INNER + 1e-5f);
#pragma unroll
    for (int k = 0; k < 16; k++) {
        int d = tid + k * 256;
        g_xn[(size_t)tok * D_INNER + d] = __uint_as_float(f2tf32(v[d] * scale * nw[d]));
    }
}

// ---------------- launch ----------------
extern "C" void kernel_launch(void* const* d_in, const int* in_sizes, int n_in,
                              void* d_out, int out_size) {
    const float* hidden  = (const float*)d_in[0];
    const float* W_in    = (const float*)d_in[1];
    const float* conv_w  = (const float*)d_in[2];
    const float* conv_b  = (const float*)d_in[3];
    const float* A       = (const float*)d_in[4];
    const float* Dsk     = (const float*)d_in[5];
    const float* dt_bias = (const float*)d_in[6];
    const float* norm_w  = (const float*)d_in[7];
    const float* W_out   = (const float*)d_in[8];
    float* out = (float*)d_out;

    void* p;
    cudaGetSymbolAddress(&p, g_zxbcdt); float* zx = (float*)p;
    cudaGetSymbolAddress(&p, g_xn);     float* xn = (float*)p;
    cudaGetSymbolAddress(&p, g_ha);     float* ha = (float*)p;
    cudaGetSymbolAddress(&p, g_wi);     float* wi = (float*)p;
    cudaGetSymbolAddress(&p, g_wo);     float* wo = (float*)p;

    round_tf32_kernel<<<(NTOK * D_MODEL / 4 + 255) / 256, 256>>>(hidden, ha, NTOK * D_MODEL);
    round_tf32_kernel<<<(D_MODEL * D_IN_PROJ / 4 + 255) / 256, 256>>>(W_in, wi, D_MODEL * D_IN_PROJ);
    round_tf32_kernel<<<(D_INNER * D_MODEL / 4 + 255) / 256, 256>>>(W_out, wo, D_INNER * D_MODEL);

    tf32gemm<<<dim3((D_IN_PROJ + 127) / 128, NTOK / 128), 256>>>(ha, wi, zx,
                                                                 NTOK, D_IN_PROJ, D_MODEL);
    conv_kernel<<<(NTOK * CONV_DIM + 255) / 256, 256>>>(conv_w, conv_b);
    dt_scan_kernel<<<dim3(NCHUNK, NHEADS, BATCH), CHUNK>>>(dt_bias, A);
    gmat_kernel<<<dim3(4, 4, BATCH * NCHUNK), 256>>>();
    ydiag_kernel<<<dim3(NCHUNK, NHEADS, BATCH), 256>>>();
    states_kernel<<<dim3(NCHUNK, NHEADS, BATCH), 256>>>();
    recur_kernel<<<(BATCH * NHEADS * D_STATE * HEAD_DIM) / 256, 256>>>();
    yoff_kernel<<<dim3(NCHUNK * 2, NHEADS, BATCH), 256>>>(Dsk);
    norm_kernel<<<NTOK, 256>>>(norm_w);
    tf32gemm<<<dim3(D_MODEL / 128, NTOK / 128), 256>>>(xn, wo, out,
                                                       NTOK, D_MODEL, D_INNER);
}